// round 12
// baseline (speedup 1.0000x reference)
#include <cuda_runtime.h>
#include <cuda_bf16.h>
#include <mma.h>
#include <cstdint>

using namespace nvcuda;

#define N_NODES 50000
#define N_PAD   50048
#define N_EDGES 800000
#define D_IN    256
#define D_HID2  256
#define D_HID   128
#define D_MLP   64
#define D_OUT   64

// ---------------- scratch ----------------
__device__ float g_hpre[(size_t)N_PAD * D_HID2];
__device__ float g_hcur[(size_t)N_PAD * D_HID2];
__device__ float g_hidden[(size_t)N_PAD * D_MLP];
__device__ float g_deg_out_inv[N_NODES];
__device__ float g_deg_in_inv[N_NODES];
__device__ int   g_deg_out_cnt[N_NODES];
__device__ int   g_deg_in_cnt[N_NODES];
__device__ int   g_row_ptr[N_NODES + 1];
__device__ int   g_fill_ptr[N_NODES];
__device__ int   g_blk[64];
__device__ int   g_csr_src[N_EDGES];

template<int SEL>
__device__ __forceinline__ const float* select_in(const float* ext) {
    if constexpr (SEL == 1) return g_hcur;
    else if constexpr (SEL == 2) return g_hidden;
    else return ext;
}
template<int SEL>
__device__ __forceinline__ float* select_out(float* ext) {
    if constexpr (SEL == 1) return g_hpre;
    else if constexpr (SEL == 2) return g_hidden;
    else return ext;
}

// ---------------- degree / CSR ----------------

__global__ void zero_counts_kernel(int n) {
    int i = blockIdx.x * blockDim.x + threadIdx.x;
    if (i < n) { g_deg_out_cnt[i] = 0; g_deg_in_cnt[i] = 0; }
}

__global__ void degree_kernel(const int* __restrict__ ei, int E) {
    int e = blockIdx.x * blockDim.x + threadIdx.x;
    if (e < E) {
        atomicAdd(&g_deg_out_cnt[ei[e]], 1);
        atomicAdd(&g_deg_in_cnt[ei[E + e]], 1);
    }
}

__global__ void inv_kernel(int n) {
    int i = blockIdx.x * blockDim.x + threadIdx.x;
    if (i < n) {
        g_deg_out_inv[i] = rsqrtf(fmaxf((float)g_deg_out_cnt[i], 1.0f));
        g_deg_in_inv[i]  = rsqrtf(fmaxf((float)g_deg_in_cnt[i], 1.0f));
    }
}

__global__ void scan1_kernel(int n) {
    __shared__ int s[1024];
    int tid = threadIdx.x;
    int i = blockIdx.x * 1024 + tid;
    int v = (i < n) ? g_deg_in_cnt[i] : 0;
    s[tid] = v;
    __syncthreads();
    #pragma unroll
    for (int off = 1; off < 1024; off <<= 1) {
        int t = 0;
        if (tid >= off) t = s[tid - off];
        __syncthreads();
        s[tid] += t;
        __syncthreads();
    }
    if (i < n) g_row_ptr[i + 1] = s[tid];
    if (tid == 1023) g_blk[blockIdx.x] = s[1023];
}

__global__ void scan2_kernel(int nb) {
    if (threadIdx.x == 0 && blockIdx.x == 0) {
        int acc = 0;
        for (int i = 0; i < nb; i++) { int t = g_blk[i]; g_blk[i] = acc; acc += t; }
    }
}

__global__ void scan3_kernel(int n) {
    int i = blockIdx.x * 1024 + threadIdx.x;
    if (i < n) g_row_ptr[i + 1] += g_blk[blockIdx.x];
    if (i == 0) g_row_ptr[0] = 0;
}

__global__ void copy_fill_kernel(int n) {
    int i = blockIdx.x * blockDim.x + threadIdx.x;
    if (i < n) g_fill_ptr[i] = g_row_ptr[i];
}

__global__ void fill_csr_kernel(const int* __restrict__ ei, int E) {
    int e = blockIdx.x * blockDim.x + threadIdx.x;
    if (e < E) {
        int d = ei[E + e];
        int pos = atomicAdd(&g_fill_ptr[d], 1);
        g_csr_src[pos] = ei[e];
    }
}

// ---------------- tf32 WMMA GEMM: C = (A * rowscale?) @ B ----------------
// BM=128, BK=32, 256 threads, 8 warps (4x2). Warp tile 32 x (BN/2).
// tf32 RN rounding at smem store; register double-buffered.
// LDA=36 / LDB=BN+4: stride mod 32 = 4 -> B frag loads conflict-free,
// A frag loads 2-way (was 4-way at stride mod 32 = 8).
template<int BN, int ASEL, int CSEL, int RS>
__global__ __launch_bounds__(256)
void gemm_tf32_kernel(const float* __restrict__ Aext, const float* __restrict__ B,
                      int M, int N, int K)
{
    constexpr int BM = 128, BK = 32;
    constexpr int LDA = BK + 4;      // 36: mod 32 = 4
    constexpr int LDB = BN + 4;      // 132 / 68: mod 32 = 4
    constexpr int WN  = BN / 2;
    constexpr int NF  = WN / 16;
    constexpr int BL  = BN / 32;
    constexpr int BC4 = BN / 4;

    const float* A = select_in<ASEL>(Aext);
    float* C = select_out<CSEL>(nullptr);

    __shared__ float As[BM][LDA];
    __shared__ float Bs[BK][LDB];

    const int tid  = threadIdx.x;
    const int warp = tid >> 5;
    const int wr   = warp >> 1;
    const int wc   = warp & 1;
    const int row0 = blockIdx.y * BM;
    const int col0 = blockIdx.x * BN;

    wmma::fragment<wmma::accumulator, 16, 16, 8, float> acc[2][NF];
    #pragma unroll
    for (int i = 0; i < 2; i++)
        #pragma unroll
        for (int j = 0; j < NF; j++) wmma::fill_fragment(acc[i][j], 0.0f);

    float4 aP[4], bP[BL];
    #pragma unroll
    for (int l = 0; l < 4; l++) {
        int lin = tid + l * 256;
        int r = lin >> 3, c4 = (lin & 7) << 2;
        int gr = row0 + r;
        float4 v = make_float4(0.f, 0.f, 0.f, 0.f);
        if (gr < M) {
            v = *(const float4*)&A[(size_t)gr * K + c4];
            if constexpr (RS) {
                float sc = g_deg_out_inv[gr];
                v.x *= sc; v.y *= sc; v.z *= sc; v.w *= sc;
            }
        }
        aP[l] = v;
    }
    #pragma unroll
    for (int l = 0; l < BL; l++) {
        int lin = tid + l * 256;
        int r = lin / BC4, c4 = (lin % BC4) * 4;
        bP[l] = *(const float4*)&B[(size_t)r * N + col0 + c4];
    }

    for (int k0 = 0; k0 < K; k0 += BK) {
        #pragma unroll
        for (int l = 0; l < 4; l++) {
            int lin = tid + l * 256;
            int r = lin >> 3, c4 = (lin & 7) << 2;
            As[r][c4 + 0] = wmma::__float_to_tf32(aP[l].x);
            As[r][c4 + 1] = wmma::__float_to_tf32(aP[l].y);
            As[r][c4 + 2] = wmma::__float_to_tf32(aP[l].z);
            As[r][c4 + 3] = wmma::__float_to_tf32(aP[l].w);
        }
        #pragma unroll
        for (int l = 0; l < BL; l++) {
            int lin = tid + l * 256;
            int r = lin / BC4, c4 = (lin % BC4) * 4;
            Bs[r][c4 + 0] = wmma::__float_to_tf32(bP[l].x);
            Bs[r][c4 + 1] = wmma::__float_to_tf32(bP[l].y);
            Bs[r][c4 + 2] = wmma::__float_to_tf32(bP[l].z);
            Bs[r][c4 + 3] = wmma::__float_to_tf32(bP[l].w);
        }
        __syncthreads();

        if (k0 + BK < K) {
            #pragma unroll
            for (int l = 0; l < 4; l++) {
                int lin = tid + l * 256;
                int r = lin >> 3, c4 = (lin & 7) << 2;
                int gr = row0 + r;
                float4 v = make_float4(0.f, 0.f, 0.f, 0.f);
                if (gr < M) {
                    v = *(const float4*)&A[(size_t)gr * K + (k0 + BK) + c4];
                    if constexpr (RS) {
                        float sc = g_deg_out_inv[gr];
                        v.x *= sc; v.y *= sc; v.z *= sc; v.w *= sc;
                    }
                }
                aP[l] = v;
            }
            #pragma unroll
            for (int l = 0; l < BL; l++) {
                int lin = tid + l * 256;
                int r = lin / BC4, c4 = (lin % BC4) * 4;
                bP[l] = *(const float4*)&B[(size_t)(k0 + BK + r) * N + col0 + c4];
            }
        }

        #pragma unroll
        for (int kk = 0; kk < BK; kk += 8) {
            wmma::fragment<wmma::matrix_a, 16, 16, 8, wmma::precision::tf32, wmma::row_major> af[2];
            #pragma unroll
            for (int i = 0; i < 2; i++)
                wmma::load_matrix_sync(af[i], &As[wr * 32 + i * 16][kk], LDA);
            wmma::fragment<wmma::matrix_b, 16, 16, 8, wmma::precision::tf32, wmma::row_major> bf[NF];
            #pragma unroll
            for (int j = 0; j < NF; j++)
                wmma::load_matrix_sync(bf[j], &Bs[kk][wc * WN + j * 16], LDB);
            #pragma unroll
            for (int i = 0; i < 2; i++)
                #pragma unroll
                for (int j = 0; j < NF; j++)
                    wmma::mma_sync(acc[i][j], af[i], bf[j], acc[i][j]);
        }
        __syncthreads();
    }

    #pragma unroll
    for (int i = 0; i < 2; i++)
        #pragma unroll
        for (int j = 0; j < NF; j++) {
            int r = row0 + wr * 32 + i * 16;
            int c = col0 + wc * WN + j * 16;
            wmma::store_matrix_sync(&C[(size_t)r * N + c], acc[i][j], N, wmma::mem_row_major);
        }
}

// ---------------- SIMT GEMM (final MLP layer; guarded d_out store) ----------------
#define GTHREADS 256
template<int BN, int ASEL, int CSEL, int USE_BIAS, int DO_RELU, int ABR>
__global__ __launch_bounds__(GTHREADS)
void gemm128_kernel(const float* __restrict__ Aext, const float* __restrict__ B,
                    float* __restrict__ Cext, int M, int N, int K,
                    const float* __restrict__ bias, const float* __restrict__ abias)
{
    constexpr int BM = 128;
    constexpr int BK = 8;
    constexpr int TM = 8;
    constexpr int TN = BN / 16;

    const float* A = select_in<ASEL>(Aext);
    float* C = select_out<CSEL>(Cext);

    __shared__ float As[BK][BM + 4];
    __shared__ float Bs[BK][BN];

    const int tid = threadIdx.x;
    const int tx = tid % 16;
    const int ty = tid / 16;
    const int row0 = blockIdx.y * BM;
    const int col0 = blockIdx.x * BN;

    const int arow = tid / 2;
    const int ac4  = (tid % 2) * 4;
    const int gA   = row0 + arow;

    const int brow = (BN == 128) ? (tid / 32) : (tid / 16);
    const int bc4  = (BN == 128) ? ((tid % 32) * 4) : ((tid % 16) * 4);
    const bool bactive = (BN == 128) ? true : (tid < 128);

    float acc[TM][TN];
    #pragma unroll
    for (int i = 0; i < TM; i++)
        #pragma unroll
        for (int j = 0; j < TN; j++) acc[i][j] = 0.0f;

    float4 av = make_float4(0.f, 0.f, 0.f, 0.f);
    if (gA < M) {
        av = *(const float4*)&A[(size_t)gA * K + ac4];
        if constexpr (ABR) {
            av.x = fmaxf(av.x + abias[ac4 + 0], 0.f);
            av.y = fmaxf(av.y + abias[ac4 + 1], 0.f);
            av.z = fmaxf(av.z + abias[ac4 + 2], 0.f);
            av.w = fmaxf(av.w + abias[ac4 + 3], 0.f);
        }
    }
    float4 bv = make_float4(0.f, 0.f, 0.f, 0.f);
    if (bactive) bv = *(const float4*)&B[(size_t)brow * N + col0 + bc4];

    for (int k0 = 0; k0 < K; k0 += BK) {
        As[ac4 + 0][arow] = av.x;
        As[ac4 + 1][arow] = av.y;
        As[ac4 + 2][arow] = av.z;
        As[ac4 + 3][arow] = av.w;
        if (bactive) *(float4*)&Bs[brow][bc4] = bv;
        __syncthreads();

        if (k0 + BK < K) {
            av = make_float4(0.f, 0.f, 0.f, 0.f);
            if (gA < M) {
                av = *(const float4*)&A[(size_t)gA * K + (k0 + BK) + ac4];
                if constexpr (ABR) {
                    av.x = fmaxf(av.x + abias[k0 + BK + ac4 + 0], 0.f);
                    av.y = fmaxf(av.y + abias[k0 + BK + ac4 + 1], 0.f);
                    av.z = fmaxf(av.z + abias[k0 + BK + ac4 + 2], 0.f);
                    av.w = fmaxf(av.w + abias[k0 + BK + ac4 + 3], 0.f);
                }
            }
            if (bactive) bv = *(const float4*)&B[(size_t)(k0 + BK + brow) * N + col0 + bc4];
        }

        #pragma unroll
        for (int k = 0; k < BK; k++) {
            float a[TM], b[TN];
            #pragma unroll
            for (int q = 0; q < TM / 4; q++)
                *(float4*)&a[q * 4] = *(const float4*)&As[k][ty * TM + q * 4];
            #pragma unroll
            for (int q = 0; q < TN / 4; q++)
                *(float4*)&b[q * 4] = *(const float4*)&Bs[k][tx * TN + q * 4];
            #pragma unroll
            for (int i = 0; i < TM; i++)
                #pragma unroll
                for (int j = 0; j < TN; j++)
                    acc[i][j] += a[i] * b[j];
        }
        __syncthreads();
    }

    #pragma unroll
    for (int i = 0; i < TM; i++) {
        int r = row0 + ty * TM + i;
        if (r >= M) continue;
        #pragma unroll
        for (int j = 0; j < TN; j += 4) {
            int c = col0 + tx * TN + j;
            float4 v = *(float4*)&acc[i][j];
            if constexpr (USE_BIAS) {
                v.x += bias[c + 0]; v.y += bias[c + 1];
                v.z += bias[c + 2]; v.w += bias[c + 3];
            }
            if constexpr (DO_RELU) {
                v.x = fmaxf(v.x, 0.f); v.y = fmaxf(v.y, 0.f);
                v.z = fmaxf(v.z, 0.f); v.w = fmaxf(v.w, 0.f);
            }
            *(float4*)&C[(size_t)r * N + c] = v;
        }
    }
}

// ---------------- aggregation (float4; 128 threads; 4-edge unroll, 2 accumulators) ----------------
template<int D, int OSEL, int PRESCALE>
__global__ __launch_bounds__(128)
void agg4_kernel(float* __restrict__ outExt, const float* __restrict__ bias)
{
    constexpr int TPN = D / 4;
    constexpr int NPB = 128 / TPN;
    float* out;
    if constexpr (OSEL == 1) out = g_hcur;
    else out = outExt;

    const int lane = threadIdx.x % TPN;
    const int node = blockIdx.x * NPB + threadIdx.x / TPN;
    if (node >= N_NODES) return;

    const int s = g_row_ptr[node];
    const int e = g_row_ptr[node + 1];
    const float4* __restrict__ hp = (const float4*)g_hpre;
    const int* __restrict__ csr = g_csr_src;

    float4 acc0 = make_float4(0.f, 0.f, 0.f, 0.f);
    float4 acc1 = make_float4(0.f, 0.f, 0.f, 0.f);
    int i = s;
    for (; i + 3 < e; i += 4) {
        int s0 = csr[i];
        int s1 = csr[i + 1];
        int s2 = csr[i + 2];
        int s3 = csr[i + 3];
        float4 v0 = hp[(size_t)s0 * TPN + lane];
        float4 v1 = hp[(size_t)s1 * TPN + lane];
        float4 v2 = hp[(size_t)s2 * TPN + lane];
        float4 v3 = hp[(size_t)s3 * TPN + lane];
        acc0.x += v0.x; acc0.y += v0.y; acc0.z += v0.z; acc0.w += v0.w;
        acc1.x += v1.x; acc1.y += v1.y; acc1.z += v1.z; acc1.w += v1.w;
        acc0.x += v2.x; acc0.y += v2.y; acc0.z += v2.z; acc0.w += v2.w;
        acc1.x += v3.x; acc1.y += v3.y; acc1.z += v3.z; acc1.w += v3.w;
    }
    for (; i < e; i++) {
        int s0 = csr[i];
        float4 v0 = hp[(size_t)s0 * TPN + lane];
        acc0.x += v0.x; acc0.y += v0.y; acc0.z += v0.z; acc0.w += v0.w;
    }
    acc0.x += acc1.x; acc0.y += acc1.y; acc0.z += acc1.z; acc0.w += acc1.w;

    const float sc = g_deg_in_inv[node];
    float osc = 1.0f;
    if constexpr (PRESCALE) osc = g_deg_out_inv[node];
    float4 bb = *(const float4*)&bias[lane * 4];
    float4 r;
    r.x = fmaxf(acc0.x * sc + bb.x, 0.f) * osc;
    r.y = fmaxf(acc0.y * sc + bb.y, 0.f) * osc;
    r.z = fmaxf(acc0.z * sc + bb.z, 0.f) * osc;
    r.w = fmaxf(acc0.w * sc + bb.w, 0.f) * osc;
    *(float4*)&out[(size_t)node * D + lane * 4] = r;
}

// ---------------- launch ----------------
extern "C" void kernel_launch(void* const* d_in, const int* in_sizes, int n_in,
                              void* d_out, int out_size)
{
    const float* x   = (const float*)d_in[0];
    const int*   ei  = (const int*)d_in[1];
    const float* W1  = (const float*)d_in[2];
    const float* b1  = (const float*)d_in[3];
    const float* W2  = (const float*)d_in[4];
    const float* b2  = (const float*)d_in[5];
    const float* W3  = (const float*)d_in[6];
    const float* b3  = (const float*)d_in[7];
    const float* mW1 = (const float*)d_in[8];
    const float* mb1 = (const float*)d_in[9];
    const float* mW2 = (const float*)d_in[10];
    const float* mb2 = (const float*)d_in[11];

    const int N = in_sizes[0] / D_IN;       // 50000
    const int E = in_sizes[1] / 2;          // 800000

    float* out      = (float*)d_out;
    float* h_last   = (float*)d_out + (size_t)N * D_OUT;

    const int T = 256;
    const int nbN = (N + T - 1) / T;
    const int nbE = (E + T - 1) / T;
    const int nbScan = (N + 1023) / 1024;
    const int tfRows = (N + 127) / 128;     // 391

    // ---- degrees (needed by layer-1 GEMM) ----
    zero_counts_kernel<<<nbN, T>>>(N);
    degree_kernel<<<nbE, T>>>(ei, E);
    inv_kernel<<<nbN, T>>>(N);

    // ---- layer-1 GEMM hoisted to 4th launch (ncu-profiled; only needs deg_out_inv) ----
    {
        dim3 grid(D_HID2 / 128, tfRows);
        gemm_tf32_kernel<128, 0, 1, 1><<<grid, 256>>>(x, W1, N, D_HID2, D_IN);
    }

    // ---- CSR build (independent of GEMM; must finish before agg1) ----
    scan1_kernel<<<nbScan, 1024>>>(N);
    scan2_kernel<<<1, 32>>>(nbScan);
    scan3_kernel<<<nbScan, 1024>>>(N);
    copy_fill_kernel<<<nbN, T>>>(N);
    fill_csr_kernel<<<nbE, T>>>(ei, E);

    // ---- layer 1 aggregation ----
    agg4_kernel<D_HID2, 1, 1><<<(N + 1) / 2, 128>>>(nullptr, b1);

    // ---- layer 2 ----
    {
        dim3 grid(D_HID2 / 128, tfRows);
        gemm_tf32_kernel<128, 1, 1, 0><<<grid, 256>>>(nullptr, W2, N, D_HID2, D_HID2);
        agg4_kernel<D_HID2, 1, 1><<<(N + 1) / 2, 128>>>(nullptr, b2);
    }
    // ---- layer 3: h_last (unscaled) directly into d_out ----
    {
        dim3 grid(D_HID / 128, tfRows);
        gemm_tf32_kernel<128, 1, 1, 0><<<grid, 256>>>(nullptr, W3, N, D_HID, D_HID2);
        agg4_kernel<D_HID, 0, 0><<<(N + 3) / 4, 128>>>(h_last, b3);
    }
    // ---- MLP layer 1 (tf32, raw GEMM into scratch) ----
    {
        dim3 grid(1, tfRows);
        gemm_tf32_kernel<64, 0, 2, 0><<<grid, 256>>>(h_last, mW1, N, D_MLP, D_HID);
    }
    // ---- MLP layer 2 (SIMT, A-side relu(a+mb1), guarded d_out store) ----
    {
        dim3 grid(D_OUT / 64, tfRows);
        gemm128_kernel<64, 2, 0, 1, 0, 1><<<grid, GTHREADS>>>(nullptr, mW2, out,
                                                              N, D_OUT, D_MLP, mb2, mb1);
    }
}

// round 13
// speedup vs baseline: 1.4757x; 1.4757x over previous
#include <cuda_runtime.h>
#include <cuda_bf16.h>
#include <mma.h>
#include <cstdint>

using namespace nvcuda;

#define N_NODES 50000
#define N_PAD   50048
#define N_EDGES 800000
#define D_IN    256
#define D_HID2  256
#define D_HID   128
#define D_MLP   64
#define D_OUT   64

// ---------------- scratch ----------------
__device__ float g_hpre[(size_t)N_PAD * D_HID2];
__device__ float g_hcur[(size_t)N_PAD * D_HID2];
__device__ float g_hidden[(size_t)N_PAD * D_MLP];
__device__ float g_deg_out_inv[N_NODES];
__device__ float g_deg_in_inv[N_NODES];
__device__ int   g_deg_out_cnt[N_NODES];
__device__ int   g_deg_in_cnt[N_NODES];
__device__ int   g_row_ptr[N_NODES + 1];
__device__ int   g_fill_ptr[N_NODES];
__device__ int   g_blk[64];
__device__ int   g_csr_src[N_EDGES];

template<int SEL>
__device__ __forceinline__ const float* select_in(const float* ext) {
    if constexpr (SEL == 1) return g_hcur;
    else if constexpr (SEL == 2) return g_hidden;
    else return ext;
}
template<int SEL>
__device__ __forceinline__ float* select_out(float* ext) {
    if constexpr (SEL == 1) return g_hpre;
    else if constexpr (SEL == 2) return g_hidden;
    else return ext;
}

// ---------------- degree / CSR ----------------

__global__ void zero_counts_kernel(int n) {
    int i = blockIdx.x * blockDim.x + threadIdx.x;
    if (i < n) { g_deg_out_cnt[i] = 0; g_deg_in_cnt[i] = 0; }
}

__global__ void degree_kernel(const int* __restrict__ ei, int E) {
    int e = blockIdx.x * blockDim.x + threadIdx.x;
    if (e < E) {
        atomicAdd(&g_deg_out_cnt[ei[e]], 1);
        atomicAdd(&g_deg_in_cnt[ei[E + e]], 1);
    }
}

__global__ void inv_kernel(int n) {
    int i = blockIdx.x * blockDim.x + threadIdx.x;
    if (i < n) {
        g_deg_out_inv[i] = rsqrtf(fmaxf((float)g_deg_out_cnt[i], 1.0f));
        g_deg_in_inv[i]  = rsqrtf(fmaxf((float)g_deg_in_cnt[i], 1.0f));
    }
}

__global__ void scan1_kernel(int n) {
    __shared__ int s[1024];
    int tid = threadIdx.x;
    int i = blockIdx.x * 1024 + tid;
    int v = (i < n) ? g_deg_in_cnt[i] : 0;
    s[tid] = v;
    __syncthreads();
    #pragma unroll
    for (int off = 1; off < 1024; off <<= 1) {
        int t = 0;
        if (tid >= off) t = s[tid - off];
        __syncthreads();
        s[tid] += t;
        __syncthreads();
    }
    if (i < n) g_row_ptr[i + 1] = s[tid];
    if (tid == 1023) g_blk[blockIdx.x] = s[1023];
}

__global__ void scan2_kernel(int nb) {
    if (threadIdx.x == 0 && blockIdx.x == 0) {
        int acc = 0;
        for (int i = 0; i < nb; i++) { int t = g_blk[i]; g_blk[i] = acc; acc += t; }
    }
}

__global__ void scan3_kernel(int n) {
    int i = blockIdx.x * 1024 + threadIdx.x;
    if (i < n) g_row_ptr[i + 1] += g_blk[blockIdx.x];
    if (i == 0) g_row_ptr[0] = 0;
}

__global__ void copy_fill_kernel(int n) {
    int i = blockIdx.x * blockDim.x + threadIdx.x;
    if (i < n) g_fill_ptr[i] = g_row_ptr[i];
}

__global__ void fill_csr_kernel(const int* __restrict__ ei, int E) {
    int e = blockIdx.x * blockDim.x + threadIdx.x;
    if (e < E) {
        int d = ei[E + e];
        int pos = atomicAdd(&g_fill_ptr[d], 1);
        g_csr_src[pos] = ei[e];
    }
}

// ---------------- tf32 WMMA GEMM (R10-proven, 256 threads, 8 warps) ----------------
// BM=128, BK=32, warp tile 32 x (BN/2). LDA=40/LDB=BN+8 (proven padding).
template<int BN, int ASEL, int CSEL, int RS>
__global__ __launch_bounds__(256)
void gemm_tf32_kernel(const float* __restrict__ Aext, const float* __restrict__ B,
                      int M, int N, int K)
{
    constexpr int BM = 128, BK = 32;
    constexpr int LDA = BK + 8;      // 40
    constexpr int LDB = BN + 8;      // 136 / 72
    constexpr int WN  = BN / 2;
    constexpr int NF  = WN / 16;
    constexpr int BL  = BN / 32;
    constexpr int BC4 = BN / 4;

    const float* A = select_in<ASEL>(Aext);
    float* C = select_out<CSEL>(nullptr);

    __shared__ float As[BM][LDA];
    __shared__ float Bs[BK][LDB];

    const int tid  = threadIdx.x;
    const int warp = tid >> 5;
    const int wr   = warp >> 1;
    const int wc   = warp & 1;
    const int row0 = blockIdx.y * BM;
    const int col0 = blockIdx.x * BN;

    wmma::fragment<wmma::accumulator, 16, 16, 8, float> acc[2][NF];
    #pragma unroll
    for (int i = 0; i < 2; i++)
        #pragma unroll
        for (int j = 0; j < NF; j++) wmma::fill_fragment(acc[i][j], 0.0f);

    float4 aP[4], bP[BL];
    #pragma unroll
    for (int l = 0; l < 4; l++) {
        int lin = tid + l * 256;
        int r = lin >> 3, c4 = (lin & 7) << 2;
        int gr = row0 + r;
        float4 v = make_float4(0.f, 0.f, 0.f, 0.f);
        if (gr < M) {
            v = *(const float4*)&A[(size_t)gr * K + c4];
            if constexpr (RS) {
                float sc = g_deg_out_inv[gr];
                v.x *= sc; v.y *= sc; v.z *= sc; v.w *= sc;
            }
        }
        aP[l] = v;
    }
    #pragma unroll
    for (int l = 0; l < BL; l++) {
        int lin = tid + l * 256;
        int r = lin / BC4, c4 = (lin % BC4) * 4;
        bP[l] = *(const float4*)&B[(size_t)r * N + col0 + c4];
    }

    for (int k0 = 0; k0 < K; k0 += BK) {
        #pragma unroll
        for (int l = 0; l < 4; l++) {
            int lin = tid + l * 256;
            int r = lin >> 3, c4 = (lin & 7) << 2;
            As[r][c4 + 0] = wmma::__float_to_tf32(aP[l].x);
            As[r][c4 + 1] = wmma::__float_to_tf32(aP[l].y);
            As[r][c4 + 2] = wmma::__float_to_tf32(aP[l].z);
            As[r][c4 + 3] = wmma::__float_to_tf32(aP[l].w);
        }
        #pragma unroll
        for (int l = 0; l < BL; l++) {
            int lin = tid + l * 256;
            int r = lin / BC4, c4 = (lin % BC4) * 4;
            Bs[r][c4 + 0] = wmma::__float_to_tf32(bP[l].x);
            Bs[r][c4 + 1] = wmma::__float_to_tf32(bP[l].y);
            Bs[r][c4 + 2] = wmma::__float_to_tf32(bP[l].z);
            Bs[r][c4 + 3] = wmma::__float_to_tf32(bP[l].w);
        }
        __syncthreads();

        if (k0 + BK < K) {
            #pragma unroll
            for (int l = 0; l < 4; l++) {
                int lin = tid + l * 256;
                int r = lin >> 3, c4 = (lin & 7) << 2;
                int gr = row0 + r;
                float4 v = make_float4(0.f, 0.f, 0.f, 0.f);
                if (gr < M) {
                    v = *(const float4*)&A[(size_t)gr * K + (k0 + BK) + c4];
                    if constexpr (RS) {
                        float sc = g_deg_out_inv[gr];
                        v.x *= sc; v.y *= sc; v.z *= sc; v.w *= sc;
                    }
                }
                aP[l] = v;
            }
            #pragma unroll
            for (int l = 0; l < BL; l++) {
                int lin = tid + l * 256;
                int r = lin / BC4, c4 = (lin % BC4) * 4;
                bP[l] = *(const float4*)&B[(size_t)(k0 + BK + r) * N + col0 + c4];
            }
        }

        #pragma unroll
        for (int kk = 0; kk < BK; kk += 8) {
            wmma::fragment<wmma::matrix_a, 16, 16, 8, wmma::precision::tf32, wmma::row_major> af[2];
            #pragma unroll
            for (int i = 0; i < 2; i++)
                wmma::load_matrix_sync(af[i], &As[wr * 32 + i * 16][kk], LDA);
            wmma::fragment<wmma::matrix_b, 16, 16, 8, wmma::precision::tf32, wmma::row_major> bf[NF];
            #pragma unroll
            for (int j = 0; j < NF; j++)
                wmma::load_matrix_sync(bf[j], &Bs[kk][wc * WN + j * 16], LDB);
            #pragma unroll
            for (int i = 0; i < 2; i++)
                #pragma unroll
                for (int j = 0; j < NF; j++)
                    wmma::mma_sync(acc[i][j], af[i], bf[j], acc[i][j]);
        }
        __syncthreads();
    }

    #pragma unroll
    for (int i = 0; i < 2; i++)
        #pragma unroll
        for (int j = 0; j < NF; j++) {
            int r = row0 + wr * 32 + i * 16;
            int c = col0 + wc * WN + j * 16;
            wmma::store_matrix_sync(&C[(size_t)r * N + c], acc[i][j], N, wmma::mem_row_major);
        }
}

// ---------------- tf32 WMMA GEMM, 512 threads / 16 warps (occupancy experiment) ----------------
// Same tile as R10 (BM=128, BN=128, BK=32, LDA=40, LDB=136), warp tile 32x32 (2x2 frags).
// Halved acc+prefetch regs/thread -> 16 warps/SM (4/SMSP) at 1 CTA/SM.
template<int ASEL, int CSEL, int RS>
__global__ __launch_bounds__(512)
void gemm_tf32_512(const float* __restrict__ Aext, const float* __restrict__ B,
                   int M, int N, int K)
{
    constexpr int BM = 128, BN = 128, BK = 32;
    constexpr int LDA = BK + 8;      // 40
    constexpr int LDB = BN + 8;      // 136

    const float* A = select_in<ASEL>(Aext);
    float* C = select_out<CSEL>(nullptr);

    __shared__ float As[BM][LDA];
    __shared__ float Bs[BK][LDB];

    const int tid  = threadIdx.x;
    const int warp = tid >> 5;       // 0..15
    const int wr   = warp >> 2;      // 0..3
    const int wc   = warp & 3;       // 0..3
    const int row0 = blockIdx.y * BM;
    const int col0 = blockIdx.x * BN;

    wmma::fragment<wmma::accumulator, 16, 16, 8, float> acc[2][2];
    #pragma unroll
    for (int i = 0; i < 2; i++)
        #pragma unroll
        for (int j = 0; j < 2; j++) wmma::fill_fragment(acc[i][j], 0.0f);

    // A: 128x32 = 1024 float4, 512 threads -> 2 each. B: 32x128 -> 2 each.
    float4 aP[2], bP[2];
    #pragma unroll
    for (int l = 0; l < 2; l++) {
        int lin = tid + l * 512;
        int r = lin >> 3, c4 = (lin & 7) << 2;
        int gr = row0 + r;
        float4 v = make_float4(0.f, 0.f, 0.f, 0.f);
        if (gr < M) {
            v = *(const float4*)&A[(size_t)gr * K + c4];
            if constexpr (RS) {
                float sc = g_deg_out_inv[gr];
                v.x *= sc; v.y *= sc; v.z *= sc; v.w *= sc;
            }
        }
        aP[l] = v;
    }
    #pragma unroll
    for (int l = 0; l < 2; l++) {
        int lin = tid + l * 512;
        int r = lin >> 5, c4 = (lin & 31) << 2;
        bP[l] = *(const float4*)&B[(size_t)r * N + col0 + c4];
    }

    for (int k0 = 0; k0 < K; k0 += BK) {
        #pragma unroll
        for (int l = 0; l < 2; l++) {
            int lin = tid + l * 512;
            int r = lin >> 3, c4 = (lin & 7) << 2;
            As[r][c4 + 0] = wmma::__float_to_tf32(aP[l].x);
            As[r][c4 + 1] = wmma::__float_to_tf32(aP[l].y);
            As[r][c4 + 2] = wmma::__float_to_tf32(aP[l].z);
            As[r][c4 + 3] = wmma::__float_to_tf32(aP[l].w);
        }
        #pragma unroll
        for (int l = 0; l < 2; l++) {
            int lin = tid + l * 512;
            int r = lin >> 5, c4 = (lin & 31) << 2;
            Bs[r][c4 + 0] = wmma::__float_to_tf32(bP[l].x);
            Bs[r][c4 + 1] = wmma::__float_to_tf32(bP[l].y);
            Bs[r][c4 + 2] = wmma::__float_to_tf32(bP[l].z);
            Bs[r][c4 + 3] = wmma::__float_to_tf32(bP[l].w);
        }
        __syncthreads();

        if (k0 + BK < K) {
            #pragma unroll
            for (int l = 0; l < 2; l++) {
                int lin = tid + l * 512;
                int r = lin >> 3, c4 = (lin & 7) << 2;
                int gr = row0 + r;
                float4 v = make_float4(0.f, 0.f, 0.f, 0.f);
                if (gr < M) {
                    v = *(const float4*)&A[(size_t)gr * K + (k0 + BK) + c4];
                    if constexpr (RS) {
                        float sc = g_deg_out_inv[gr];
                        v.x *= sc; v.y *= sc; v.z *= sc; v.w *= sc;
                    }
                }
                aP[l] = v;
            }
            #pragma unroll
            for (int l = 0; l < 2; l++) {
                int lin = tid + l * 512;
                int r = lin >> 5, c4 = (lin & 31) << 2;
                bP[l] = *(const float4*)&B[(size_t)(k0 + BK + r) * N + col0 + c4];
            }
        }

        #pragma unroll
        for (int kk = 0; kk < BK; kk += 8) {
            wmma::fragment<wmma::matrix_a, 16, 16, 8, wmma::precision::tf32, wmma::row_major> af[2];
            #pragma unroll
            for (int i = 0; i < 2; i++)
                wmma::load_matrix_sync(af[i], &As[wr * 32 + i * 16][kk], LDA);
            wmma::fragment<wmma::matrix_b, 16, 16, 8, wmma::precision::tf32, wmma::row_major> bf[2];
            #pragma unroll
            for (int j = 0; j < 2; j++)
                wmma::load_matrix_sync(bf[j], &Bs[kk][wc * 32 + j * 16], LDB);
            #pragma unroll
            for (int i = 0; i < 2; i++)
                #pragma unroll
                for (int j = 0; j < 2; j++)
                    wmma::mma_sync(acc[i][j], af[i], bf[j], acc[i][j]);
        }
        __syncthreads();
    }

    #pragma unroll
    for (int i = 0; i < 2; i++)
        #pragma unroll
        for (int j = 0; j < 2; j++) {
            int r = row0 + wr * 32 + i * 16;
            int c = col0 + wc * 32 + j * 16;
            wmma::store_matrix_sync(&C[(size_t)r * N + c], acc[i][j], N, wmma::mem_row_major);
        }
}

// ---------------- SIMT GEMM (final MLP layer; guarded d_out store) ----------------
#define GTHREADS 256
template<int BN, int ASEL, int CSEL, int USE_BIAS, int DO_RELU, int ABR>
__global__ __launch_bounds__(GTHREADS)
void gemm128_kernel(const float* __restrict__ Aext, const float* __restrict__ B,
                    float* __restrict__ Cext, int M, int N, int K,
                    const float* __restrict__ bias, const float* __restrict__ abias)
{
    constexpr int BM = 128;
    constexpr int BK = 8;
    constexpr int TM = 8;
    constexpr int TN = BN / 16;

    const float* A = select_in<ASEL>(Aext);
    float* C = select_out<CSEL>(Cext);

    __shared__ float As[BK][BM + 4];
    __shared__ float Bs[BK][BN];

    const int tid = threadIdx.x;
    const int tx = tid % 16;
    const int ty = tid / 16;
    const int row0 = blockIdx.y * BM;
    const int col0 = blockIdx.x * BN;

    const int arow = tid / 2;
    const int ac4  = (tid % 2) * 4;
    const int gA   = row0 + arow;

    const int brow = (BN == 128) ? (tid / 32) : (tid / 16);
    const int bc4  = (BN == 128) ? ((tid % 32) * 4) : ((tid % 16) * 4);
    const bool bactive = (BN == 128) ? true : (tid < 128);

    float acc[TM][TN];
    #pragma unroll
    for (int i = 0; i < TM; i++)
        #pragma unroll
        for (int j = 0; j < TN; j++) acc[i][j] = 0.0f;

    float4 av = make_float4(0.f, 0.f, 0.f, 0.f);
    if (gA < M) {
        av = *(const float4*)&A[(size_t)gA * K + ac4];
        if constexpr (ABR) {
            av.x = fmaxf(av.x + abias[ac4 + 0], 0.f);
            av.y = fmaxf(av.y + abias[ac4 + 1], 0.f);
            av.z = fmaxf(av.z + abias[ac4 + 2], 0.f);
            av.w = fmaxf(av.w + abias[ac4 + 3], 0.f);
        }
    }
    float4 bv = make_float4(0.f, 0.f, 0.f, 0.f);
    if (bactive) bv = *(const float4*)&B[(size_t)brow * N + col0 + bc4];

    for (int k0 = 0; k0 < K; k0 += BK) {
        As[ac4 + 0][arow] = av.x;
        As[ac4 + 1][arow] = av.y;
        As[ac4 + 2][arow] = av.z;
        As[ac4 + 3][arow] = av.w;
        if (bactive) *(float4*)&Bs[brow][bc4] = bv;
        __syncthreads();

        if (k0 + BK < K) {
            av = make_float4(0.f, 0.f, 0.f, 0.f);
            if (gA < M) {
                av = *(const float4*)&A[(size_t)gA * K + (k0 + BK) + ac4];
                if constexpr (ABR) {
                    av.x = fmaxf(av.x + abias[k0 + BK + ac4 + 0], 0.f);
                    av.y = fmaxf(av.y + abias[k0 + BK + ac4 + 1], 0.f);
                    av.z = fmaxf(av.z + abias[k0 + BK + ac4 + 2], 0.f);
                    av.w = fmaxf(av.w + abias[k0 + BK + ac4 + 3], 0.f);
                }
            }
            if (bactive) bv = *(const float4*)&B[(size_t)(k0 + BK + brow) * N + col0 + bc4];
        }

        #pragma unroll
        for (int k = 0; k < BK; k++) {
            float a[TM], b[TN];
            #pragma unroll
            for (int q = 0; q < TM / 4; q++)
                *(float4*)&a[q * 4] = *(const float4*)&As[k][ty * TM + q * 4];
            #pragma unroll
            for (int q = 0; q < TN / 4; q++)
                *(float4*)&b[q * 4] = *(const float4*)&Bs[k][tx * TN + q * 4];
            #pragma unroll
            for (int i = 0; i < TM; i++)
                #pragma unroll
                for (int j = 0; j < TN; j++)
                    acc[i][j] += a[i] * b[j];
        }
        __syncthreads();
    }

    #pragma unroll
    for (int i = 0; i < TM; i++) {
        int r = row0 + ty * TM + i;
        if (r >= M) continue;
        #pragma unroll
        for (int j = 0; j < TN; j += 4) {
            int c = col0 + tx * TN + j;
            float4 v = *(float4*)&acc[i][j];
            if constexpr (USE_BIAS) {
                v.x += bias[c + 0]; v.y += bias[c + 1];
                v.z += bias[c + 2]; v.w += bias[c + 3];
            }
            if constexpr (DO_RELU) {
                v.x = fmaxf(v.x, 0.f); v.y = fmaxf(v.y, 0.f);
                v.z = fmaxf(v.z, 0.f); v.w = fmaxf(v.w, 0.f);
            }
            *(float4*)&C[(size_t)r * N + c] = v;
        }
    }
}

// ---------------- aggregation (float4; 128 threads; 4-edge unroll, 2 accumulators) ----------------
template<int D, int OSEL, int PRESCALE>
__global__ __launch_bounds__(128)
void agg4_kernel(float* __restrict__ outExt, const float* __restrict__ bias)
{
    constexpr int TPN = D / 4;
    constexpr int NPB = 128 / TPN;
    float* out;
    if constexpr (OSEL == 1) out = g_hcur;
    else out = outExt;

    const int lane = threadIdx.x % TPN;
    const int node = blockIdx.x * NPB + threadIdx.x / TPN;
    if (node >= N_NODES) return;

    const int s = g_row_ptr[node];
    const int e = g_row_ptr[node + 1];
    const float4* __restrict__ hp = (const float4*)g_hpre;
    const int* __restrict__ csr = g_csr_src;

    float4 acc0 = make_float4(0.f, 0.f, 0.f, 0.f);
    float4 acc1 = make_float4(0.f, 0.f, 0.f, 0.f);
    int i = s;
    for (; i + 3 < e; i += 4) {
        int s0 = csr[i];
        int s1 = csr[i + 1];
        int s2 = csr[i + 2];
        int s3 = csr[i + 3];
        float4 v0 = hp[(size_t)s0 * TPN + lane];
        float4 v1 = hp[(size_t)s1 * TPN + lane];
        float4 v2 = hp[(size_t)s2 * TPN + lane];
        float4 v3 = hp[(size_t)s3 * TPN + lane];
        acc0.x += v0.x; acc0.y += v0.y; acc0.z += v0.z; acc0.w += v0.w;
        acc1.x += v1.x; acc1.y += v1.y; acc1.z += v1.z; acc1.w += v1.w;
        acc0.x += v2.x; acc0.y += v2.y; acc0.z += v2.z; acc0.w += v2.w;
        acc1.x += v3.x; acc1.y += v3.y; acc1.z += v3.z; acc1.w += v3.w;
    }
    for (; i < e; i++) {
        int s0 = csr[i];
        float4 v0 = hp[(size_t)s0 * TPN + lane];
        acc0.x += v0.x; acc0.y += v0.y; acc0.z += v0.z; acc0.w += v0.w;
    }
    acc0.x += acc1.x; acc0.y += acc1.y; acc0.z += acc1.z; acc0.w += acc1.w;

    const float sc = g_deg_in_inv[node];
    float osc = 1.0f;
    if constexpr (PRESCALE) osc = g_deg_out_inv[node];
    float4 bb = *(const float4*)&bias[lane * 4];
    float4 r;
    r.x = fmaxf(acc0.x * sc + bb.x, 0.f) * osc;
    r.y = fmaxf(acc0.y * sc + bb.y, 0.f) * osc;
    r.z = fmaxf(acc0.z * sc + bb.z, 0.f) * osc;
    r.w = fmaxf(acc0.w * sc + bb.w, 0.f) * osc;
    *(float4*)&out[(size_t)node * D + lane * 4] = r;
}

// ---------------- launch ----------------
extern "C" void kernel_launch(void* const* d_in, const int* in_sizes, int n_in,
                              void* d_out, int out_size)
{
    const float* x   = (const float*)d_in[0];
    const int*   ei  = (const int*)d_in[1];
    const float* W1  = (const float*)d_in[2];
    const float* b1  = (const float*)d_in[3];
    const float* W2  = (const float*)d_in[4];
    const float* b2  = (const float*)d_in[5];
    const float* W3  = (const float*)d_in[6];
    const float* b3  = (const float*)d_in[7];
    const float* mW1 = (const float*)d_in[8];
    const float* mb1 = (const float*)d_in[9];
    const float* mW2 = (const float*)d_in[10];
    const float* mb2 = (const float*)d_in[11];

    const int N = in_sizes[0] / D_IN;       // 50000
    const int E = in_sizes[1] / 2;          // 800000

    float* out      = (float*)d_out;
    float* h_last   = (float*)d_out + (size_t)N * D_OUT;

    const int T = 256;
    const int nbN = (N + T - 1) / T;
    const int nbE = (E + T - 1) / T;
    const int nbScan = (N + 1023) / 1024;
    const int tfRows = (N + 127) / 128;     // 391

    // ---- degrees (needed by layer-1 GEMM) ----
    zero_counts_kernel<<<nbN, T>>>(N);
    degree_kernel<<<nbE, T>>>(ei, E);
    inv_kernel<<<nbN, T>>>(N);

    // ---- layer-1 GEMM (512-thread experiment; 4th launch -> ncu-profiled) ----
    {
        dim3 grid(D_HID2 / 128, tfRows);
        gemm_tf32_512<0, 1, 1><<<grid, 512>>>(x, W1, N, D_HID2, D_IN);
    }

    // ---- CSR build (independent of GEMM; must finish before agg1) ----
    scan1_kernel<<<nbScan, 1024>>>(N);
    scan2_kernel<<<1, 32>>>(nbScan);
    scan3_kernel<<<nbScan, 1024>>>(N);
    copy_fill_kernel<<<nbN, T>>>(N);
    fill_csr_kernel<<<nbE, T>>>(ei, E);

    // ---- layer 1 aggregation ----
    agg4_kernel<D_HID2, 1, 1><<<(N + 1) / 2, 128>>>(nullptr, b1);

    // ---- layer 2 (512-thread experiment) ----
    {
        dim3 grid(D_HID2 / 128, tfRows);
        gemm_tf32_512<1, 1, 0><<<grid, 512>>>(nullptr, W2, N, D_HID2, D_HID2);
        agg4_kernel<D_HID2, 1, 1><<<(N + 1) / 2, 128>>>(nullptr, b2);
    }
    // ---- layer 3: R10-proven 256-thread kernel; h_last directly into d_out ----
    {
        dim3 grid(D_HID / 128, tfRows);
        gemm_tf32_kernel<128, 1, 1, 0><<<grid, 256>>>(nullptr, W3, N, D_HID, D_HID2);
        agg4_kernel<D_HID, 0, 0><<<(N + 3) / 4, 128>>>(h_last, b3);
    }
    // ---- MLP layer 1 (tf32, raw GEMM into scratch) ----
    {
        dim3 grid(1, tfRows);
        gemm_tf32_kernel<64, 0, 2, 0><<<grid, 256>>>(h_last, mW1, N, D_MLP, D_HID);
    }
    // ---- MLP layer 2 (SIMT, A-side relu(a+mb1), guarded d_out store) ----
    {
        dim3 grid(D_OUT / 64, tfRows);
        gemm128_kernel<64, 2, 0, 1, 0, 1><<<grid, GTHREADS>>>(nullptr, mW2, out,
                                                              N, D_OUT, D_MLP, mb2, mb1);
    }
}

// round 14
// speedup vs baseline: 1.5331x; 1.0389x over previous
#include <cuda_runtime.h>
#include <cuda_bf16.h>
#include <mma.h>
#include <cstdint>

using namespace nvcuda;

#define N_NODES 50000
#define N_PAD   50048
#define N_EDGES 800000
#define D_IN    256
#define D_HID2  256
#define D_HID   128
#define D_MLP   64
#define D_OUT   64

// ---------------- scratch ----------------
__device__ float g_hpre[(size_t)N_PAD * D_HID2];
__device__ float g_hcur[(size_t)N_PAD * D_HID2];
__device__ float g_hidden[(size_t)N_PAD * D_MLP];
__device__ float g_deg_out_inv[N_NODES];
__device__ float g_deg_in_inv[N_NODES];
__device__ int   g_deg_out_cnt[N_NODES];
__device__ int   g_deg_in_cnt[N_NODES];
__device__ int   g_row_ptr[N_NODES + 1];
__device__ int   g_fill_ptr[N_NODES];
__device__ int   g_blk[64];
__device__ int   g_csr_src[N_EDGES];

template<int SEL>
__device__ __forceinline__ const float* select_in(const float* ext) {
    if constexpr (SEL == 1) return g_hcur;
    else if constexpr (SEL == 2) return g_hidden;
    else return ext;
}
template<int SEL>
__device__ __forceinline__ float* select_out(float* ext) {
    if constexpr (SEL == 1) return g_hpre;
    else if constexpr (SEL == 2) return g_hidden;
    else return ext;
}

// ---------------- degree / CSR ----------------

__global__ void zero_counts_kernel(int n) {
    int i = blockIdx.x * blockDim.x + threadIdx.x;
    if (i < n) { g_deg_out_cnt[i] = 0; g_deg_in_cnt[i] = 0; }
}

__global__ void degree_kernel(const int* __restrict__ ei, int E) {
    int e = blockIdx.x * blockDim.x + threadIdx.x;
    if (e < E) {
        atomicAdd(&g_deg_out_cnt[ei[e]], 1);
        atomicAdd(&g_deg_in_cnt[ei[E + e]], 1);
    }
}

__global__ void inv_kernel(int n) {
    int i = blockIdx.x * blockDim.x + threadIdx.x;
    if (i < n) {
        g_deg_out_inv[i] = rsqrtf(fmaxf((float)g_deg_out_cnt[i], 1.0f));
        g_deg_in_inv[i]  = rsqrtf(fmaxf((float)g_deg_in_cnt[i], 1.0f));
    }
}

__global__ void scan1_kernel(int n) {
    __shared__ int s[1024];
    int tid = threadIdx.x;
    int i = blockIdx.x * 1024 + tid;
    int v = (i < n) ? g_deg_in_cnt[i] : 0;
    s[tid] = v;
    __syncthreads();
    #pragma unroll
    for (int off = 1; off < 1024; off <<= 1) {
        int t = 0;
        if (tid >= off) t = s[tid - off];
        __syncthreads();
        s[tid] += t;
        __syncthreads();
    }
    if (i < n) g_row_ptr[i + 1] = s[tid];
    if (tid == 1023) g_blk[blockIdx.x] = s[1023];
}

__global__ void scan2_kernel(int nb) {
    if (threadIdx.x == 0 && blockIdx.x == 0) {
        int acc = 0;
        for (int i = 0; i < nb; i++) { int t = g_blk[i]; g_blk[i] = acc; acc += t; }
    }
}

__global__ void scan3_kernel(int n) {
    int i = blockIdx.x * 1024 + threadIdx.x;
    if (i < n) g_row_ptr[i + 1] += g_blk[blockIdx.x];
    if (i == 0) g_row_ptr[0] = 0;
}

__global__ void copy_fill_kernel(int n) {
    int i = blockIdx.x * blockDim.x + threadIdx.x;
    if (i < n) g_fill_ptr[i] = g_row_ptr[i];
}

__global__ void fill_csr_kernel(const int* __restrict__ ei, int E) {
    int e = blockIdx.x * blockDim.x + threadIdx.x;
    if (e < E) {
        int d = ei[E + e];
        int pos = atomicAdd(&g_fill_ptr[d], 1);
        g_csr_src[pos] = ei[e];
    }
}

// ---------------- tf32 WMMA GEMM, wide tile: BM=128 x BN=256 x BK=16, 512 thr ----------------
// 16 warps as 4x4, warp tile 32x64 (af[2], bf[4], 8 mma -> 0.75 LDS/MMA ratio
// at 16-warp occupancy). Requires N == 256. RN tf32 at smem store; reg prefetch.
template<int ASEL, int CSEL, int RS>
__global__ __launch_bounds__(512)
void gemm_tf32_w256(const float* __restrict__ Aext, const float* __restrict__ B,
                    int M, int K)
{
    constexpr int N = 256;
    constexpr int BM = 128, BN = 256, BK = 16;
    constexpr int LDA = BK + 8;      // 24
    constexpr int LDB = BN + 8;      // 264

    const float* A = select_in<ASEL>(Aext);
    float* C = select_out<CSEL>(nullptr);

    __shared__ float As[BM][LDA];    // 128*24*4 = 12.3 KB
    __shared__ float Bs[BK][LDB];    // 16*264*4 = 16.9 KB

    const int tid  = threadIdx.x;
    const int warp = tid >> 5;       // 0..15
    const int wr   = warp >> 2;      // 0..3 -> row * 32
    const int wc   = warp & 3;       // 0..3 -> col * 64
    const int row0 = blockIdx.y * BM;

    wmma::fragment<wmma::accumulator, 16, 16, 8, float> acc[2][4];
    #pragma unroll
    for (int i = 0; i < 2; i++)
        #pragma unroll
        for (int j = 0; j < 4; j++) wmma::fill_fragment(acc[i][j], 0.0f);

    // A: 128x16 = 512 float4 -> 1 per thread. B: 16x256 = 1024 float4 -> 2 per thread.
    const int ar = tid >> 2;                  // 0..127
    const int ac4 = (tid & 3) << 2;           // 0,4,8,12
    float4 aP, bP[2];

    {
        int gr = row0 + ar;
        float4 v = make_float4(0.f, 0.f, 0.f, 0.f);
        if (gr < M) {
            v = *(const float4*)&A[(size_t)gr * K + ac4];
            if constexpr (RS) {
                float sc = g_deg_out_inv[gr];
                v.x *= sc; v.y *= sc; v.z *= sc; v.w *= sc;
            }
        }
        aP = v;
    }
    #pragma unroll
    for (int l = 0; l < 2; l++) {
        int lin = tid + l * 512;
        int r = lin >> 6, c4 = (lin & 63) << 2;
        bP[l] = *(const float4*)&B[(size_t)r * N + c4];
    }

    for (int k0 = 0; k0 < K; k0 += BK) {
        As[ar][ac4 + 0] = wmma::__float_to_tf32(aP.x);
        As[ar][ac4 + 1] = wmma::__float_to_tf32(aP.y);
        As[ar][ac4 + 2] = wmma::__float_to_tf32(aP.z);
        As[ar][ac4 + 3] = wmma::__float_to_tf32(aP.w);
        #pragma unroll
        for (int l = 0; l < 2; l++) {
            int lin = tid + l * 512;
            int r = lin >> 6, c4 = (lin & 63) << 2;
            Bs[r][c4 + 0] = wmma::__float_to_tf32(bP[l].x);
            Bs[r][c4 + 1] = wmma::__float_to_tf32(bP[l].y);
            Bs[r][c4 + 2] = wmma::__float_to_tf32(bP[l].z);
            Bs[r][c4 + 3] = wmma::__float_to_tf32(bP[l].w);
        }
        __syncthreads();

        if (k0 + BK < K) {
            int gr = row0 + ar;
            float4 v = make_float4(0.f, 0.f, 0.f, 0.f);
            if (gr < M) {
                v = *(const float4*)&A[(size_t)gr * K + (k0 + BK) + ac4];
                if constexpr (RS) {
                    float sc = g_deg_out_inv[gr];
                    v.x *= sc; v.y *= sc; v.z *= sc; v.w *= sc;
                }
            }
            aP = v;
            #pragma unroll
            for (int l = 0; l < 2; l++) {
                int lin = tid + l * 512;
                int r = lin >> 6, c4 = (lin & 63) << 2;
                bP[l] = *(const float4*)&B[(size_t)(k0 + BK + r) * N + c4];
            }
        }

        #pragma unroll
        for (int kk = 0; kk < BK; kk += 8) {
            wmma::fragment<wmma::matrix_a, 16, 16, 8, wmma::precision::tf32, wmma::row_major> af[2];
            #pragma unroll
            for (int i = 0; i < 2; i++)
                wmma::load_matrix_sync(af[i], &As[wr * 32 + i * 16][kk], LDA);
            wmma::fragment<wmma::matrix_b, 16, 16, 8, wmma::precision::tf32, wmma::row_major> bf[4];
            #pragma unroll
            for (int j = 0; j < 4; j++)
                wmma::load_matrix_sync(bf[j], &Bs[kk][wc * 64 + j * 16], LDB);
            #pragma unroll
            for (int i = 0; i < 2; i++)
                #pragma unroll
                for (int j = 0; j < 4; j++)
                    wmma::mma_sync(acc[i][j], af[i], bf[j], acc[i][j]);
        }
        __syncthreads();
    }

    #pragma unroll
    for (int i = 0; i < 2; i++)
        #pragma unroll
        for (int j = 0; j < 4; j++) {
            int r = row0 + wr * 32 + i * 16;
            int c = wc * 64 + j * 16;
            wmma::store_matrix_sync(&C[(size_t)r * N + c], acc[i][j], N, wmma::mem_row_major);
        }
}

// ---------------- tf32 WMMA GEMM, 512 threads / 16 warps (R13-proven, BN=128) ----------------
template<int ASEL, int CSEL, int RS>
__global__ __launch_bounds__(512)
void gemm_tf32_512(const float* __restrict__ Aext, const float* __restrict__ B,
                   int M, int N, int K)
{
    constexpr int BM = 128, BN = 128, BK = 32;
    constexpr int LDA = BK + 8;      // 40
    constexpr int LDB = BN + 8;      // 136

    const float* A = select_in<ASEL>(Aext);
    float* C = select_out<CSEL>(nullptr);

    __shared__ float As[BM][LDA];
    __shared__ float Bs[BK][LDB];

    const int tid  = threadIdx.x;
    const int warp = tid >> 5;
    const int wr   = warp >> 2;
    const int wc   = warp & 3;
    const int row0 = blockIdx.y * BM;
    const int col0 = blockIdx.x * BN;

    wmma::fragment<wmma::accumulator, 16, 16, 8, float> acc[2][2];
    #pragma unroll
    for (int i = 0; i < 2; i++)
        #pragma unroll
        for (int j = 0; j < 2; j++) wmma::fill_fragment(acc[i][j], 0.0f);

    float4 aP[2], bP[2];
    #pragma unroll
    for (int l = 0; l < 2; l++) {
        int lin = tid + l * 512;
        int r = lin >> 3, c4 = (lin & 7) << 2;
        int gr = row0 + r;
        float4 v = make_float4(0.f, 0.f, 0.f, 0.f);
        if (gr < M) {
            v = *(const float4*)&A[(size_t)gr * K + c4];
            if constexpr (RS) {
                float sc = g_deg_out_inv[gr];
                v.x *= sc; v.y *= sc; v.z *= sc; v.w *= sc;
            }
        }
        aP[l] = v;
    }
    #pragma unroll
    for (int l = 0; l < 2; l++) {
        int lin = tid + l * 512;
        int r = lin >> 5, c4 = (lin & 31) << 2;
        bP[l] = *(const float4*)&B[(size_t)r * N + col0 + c4];
    }

    for (int k0 = 0; k0 < K; k0 += BK) {
        #pragma unroll
        for (int l = 0; l < 2; l++) {
            int lin = tid + l * 512;
            int r = lin >> 3, c4 = (lin & 7) << 2;
            As[r][c4 + 0] = wmma::__float_to_tf32(aP[l].x);
            As[r][c4 + 1] = wmma::__float_to_tf32(aP[l].y);
            As[r][c4 + 2] = wmma::__float_to_tf32(aP[l].z);
            As[r][c4 + 3] = wmma::__float_to_tf32(aP[l].w);
        }
        #pragma unroll
        for (int l = 0; l < 2; l++) {
            int lin = tid + l * 512;
            int r = lin >> 5, c4 = (lin & 31) << 2;
            Bs[r][c4 + 0] = wmma::__float_to_tf32(bP[l].x);
            Bs[r][c4 + 1] = wmma::__float_to_tf32(bP[l].y);
            Bs[r][c4 + 2] = wmma::__float_to_tf32(bP[l].z);
            Bs[r][c4 + 3] = wmma::__float_to_tf32(bP[l].w);
        }
        __syncthreads();

        if (k0 + BK < K) {
            #pragma unroll
            for (int l = 0; l < 2; l++) {
                int lin = tid + l * 512;
                int r = lin >> 3, c4 = (lin & 7) << 2;
                int gr = row0 + r;
                float4 v = make_float4(0.f, 0.f, 0.f, 0.f);
                if (gr < M) {
                    v = *(const float4*)&A[(size_t)gr * K + (k0 + BK) + c4];
                    if constexpr (RS) {
                        float sc = g_deg_out_inv[gr];
                        v.x *= sc; v.y *= sc; v.z *= sc; v.w *= sc;
                    }
                }
                aP[l] = v;
            }
            #pragma unroll
            for (int l = 0; l < 2; l++) {
                int lin = tid + l * 512;
                int r = lin >> 5, c4 = (lin & 31) << 2;
                bP[l] = *(const float4*)&B[(size_t)(k0 + BK + r) * N + col0 + c4];
            }
        }

        #pragma unroll
        for (int kk = 0; kk < BK; kk += 8) {
            wmma::fragment<wmma::matrix_a, 16, 16, 8, wmma::precision::tf32, wmma::row_major> af[2];
            #pragma unroll
            for (int i = 0; i < 2; i++)
                wmma::load_matrix_sync(af[i], &As[wr * 32 + i * 16][kk], LDA);
            wmma::fragment<wmma::matrix_b, 16, 16, 8, wmma::precision::tf32, wmma::row_major> bf[2];
            #pragma unroll
            for (int j = 0; j < 2; j++)
                wmma::load_matrix_sync(bf[j], &Bs[kk][wc * 32 + j * 16], LDB);
            #pragma unroll
            for (int i = 0; i < 2; i++)
                #pragma unroll
                for (int j = 0; j < 2; j++)
                    wmma::mma_sync(acc[i][j], af[i], bf[j], acc[i][j]);
        }
        __syncthreads();
    }

    #pragma unroll
    for (int i = 0; i < 2; i++)
        #pragma unroll
        for (int j = 0; j < 2; j++) {
            int r = row0 + wr * 32 + i * 16;
            int c = col0 + wc * 32 + j * 16;
            wmma::store_matrix_sync(&C[(size_t)r * N + c], acc[i][j], N, wmma::mem_row_major);
        }
}

// ---------------- tf32 WMMA GEMM (R10-proven, 256 threads; used for MLP1 BN=64) ----------------
template<int BN, int ASEL, int CSEL, int RS>
__global__ __launch_bounds__(256)
void gemm_tf32_kernel(const float* __restrict__ Aext, const float* __restrict__ B,
                      int M, int N, int K)
{
    constexpr int BM = 128, BK = 32;
    constexpr int LDA = BK + 8;
    constexpr int LDB = BN + 8;
    constexpr int WN  = BN / 2;
    constexpr int NF  = WN / 16;
    constexpr int BL  = BN / 32;
    constexpr int BC4 = BN / 4;

    const float* A = select_in<ASEL>(Aext);
    float* C = select_out<CSEL>(nullptr);

    __shared__ float As[BM][LDA];
    __shared__ float Bs[BK][LDB];

    const int tid  = threadIdx.x;
    const int warp = tid >> 5;
    const int wr   = warp >> 1;
    const int wc   = warp & 1;
    const int row0 = blockIdx.y * BM;
    const int col0 = blockIdx.x * BN;

    wmma::fragment<wmma::accumulator, 16, 16, 8, float> acc[2][NF];
    #pragma unroll
    for (int i = 0; i < 2; i++)
        #pragma unroll
        for (int j = 0; j < NF; j++) wmma::fill_fragment(acc[i][j], 0.0f);

    float4 aP[4], bP[BL];
    #pragma unroll
    for (int l = 0; l < 4; l++) {
        int lin = tid + l * 256;
        int r = lin >> 3, c4 = (lin & 7) << 2;
        int gr = row0 + r;
        float4 v = make_float4(0.f, 0.f, 0.f, 0.f);
        if (gr < M) {
            v = *(const float4*)&A[(size_t)gr * K + c4];
            if constexpr (RS) {
                float sc = g_deg_out_inv[gr];
                v.x *= sc; v.y *= sc; v.z *= sc; v.w *= sc;
            }
        }
        aP[l] = v;
    }
    #pragma unroll
    for (int l = 0; l < BL; l++) {
        int lin = tid + l * 256;
        int r = lin / BC4, c4 = (lin % BC4) * 4;
        bP[l] = *(const float4*)&B[(size_t)r * N + col0 + c4];
    }

    for (int k0 = 0; k0 < K; k0 += BK) {
        #pragma unroll
        for (int l = 0; l < 4; l++) {
            int lin = tid + l * 256;
            int r = lin >> 3, c4 = (lin & 7) << 2;
            As[r][c4 + 0] = wmma::__float_to_tf32(aP[l].x);
            As[r][c4 + 1] = wmma::__float_to_tf32(aP[l].y);
            As[r][c4 + 2] = wmma::__float_to_tf32(aP[l].z);
            As[r][c4 + 3] = wmma::__float_to_tf32(aP[l].w);
        }
        #pragma unroll
        for (int l = 0; l < BL; l++) {
            int lin = tid + l * 256;
            int r = lin / BC4, c4 = (lin % BC4) * 4;
            Bs[r][c4 + 0] = wmma::__float_to_tf32(bP[l].x);
            Bs[r][c4 + 1] = wmma::__float_to_tf32(bP[l].y);
            Bs[r][c4 + 2] = wmma::__float_to_tf32(bP[l].z);
            Bs[r][c4 + 3] = wmma::__float_to_tf32(bP[l].w);
        }
        __syncthreads();

        if (k0 + BK < K) {
            #pragma unroll
            for (int l = 0; l < 4; l++) {
                int lin = tid + l * 256;
                int r = lin >> 3, c4 = (lin & 7) << 2;
                int gr = row0 + r;
                float4 v = make_float4(0.f, 0.f, 0.f, 0.f);
                if (gr < M) {
                    v = *(const float4*)&A[(size_t)gr * K + (k0 + BK) + c4];
                    if constexpr (RS) {
                        float sc = g_deg_out_inv[gr];
                        v.x *= sc; v.y *= sc; v.z *= sc; v.w *= sc;
                    }
                }
                aP[l] = v;
            }
            #pragma unroll
            for (int l = 0; l < BL; l++) {
                int lin = tid + l * 256;
                int r = lin / BC4, c4 = (lin % BC4) * 4;
                bP[l] = *(const float4*)&B[(size_t)(k0 + BK + r) * N + col0 + c4];
            }
        }

        #pragma unroll
        for (int kk = 0; kk < BK; kk += 8) {
            wmma::fragment<wmma::matrix_a, 16, 16, 8, wmma::precision::tf32, wmma::row_major> af[2];
            #pragma unroll
            for (int i = 0; i < 2; i++)
                wmma::load_matrix_sync(af[i], &As[wr * 32 + i * 16][kk], LDA);
            wmma::fragment<wmma::matrix_b, 16, 16, 8, wmma::precision::tf32, wmma::row_major> bf[NF];
            #pragma unroll
            for (int j = 0; j < NF; j++)
                wmma::load_matrix_sync(bf[j], &Bs[kk][wc * WN + j * 16], LDB);
            #pragma unroll
            for (int i = 0; i < 2; i++)
                #pragma unroll
                for (int j = 0; j < NF; j++)
                    wmma::mma_sync(acc[i][j], af[i], bf[j], acc[i][j]);
        }
        __syncthreads();
    }

    #pragma unroll
    for (int i = 0; i < 2; i++)
        #pragma unroll
        for (int j = 0; j < NF; j++) {
            int r = row0 + wr * 32 + i * 16;
            int c = col0 + wc * WN + j * 16;
            wmma::store_matrix_sync(&C[(size_t)r * N + c], acc[i][j], N, wmma::mem_row_major);
        }
}

// ---------------- SIMT GEMM (final MLP layer; guarded d_out store) ----------------
#define GTHREADS 256
template<int BN, int ASEL, int CSEL, int USE_BIAS, int DO_RELU, int ABR>
__global__ __launch_bounds__(GTHREADS)
void gemm128_kernel(const float* __restrict__ Aext, const float* __restrict__ B,
                    float* __restrict__ Cext, int M, int N, int K,
                    const float* __restrict__ bias, const float* __restrict__ abias)
{
    constexpr int BM = 128;
    constexpr int BK = 8;
    constexpr int TM = 8;
    constexpr int TN = BN / 16;

    const float* A = select_in<ASEL>(Aext);
    float* C = select_out<CSEL>(Cext);

    __shared__ float As[BK][BM + 4];
    __shared__ float Bs[BK][BN];

    const int tid = threadIdx.x;
    const int tx = tid % 16;
    const int ty = tid / 16;
    const int row0 = blockIdx.y * BM;
    const int col0 = blockIdx.x * BN;

    const int arow = tid / 2;
    const int ac4  = (tid % 2) * 4;
    const int gA   = row0 + arow;

    const int brow = (BN == 128) ? (tid / 32) : (tid / 16);
    const int bc4  = (BN == 128) ? ((tid % 32) * 4) : ((tid % 16) * 4);
    const bool bactive = (BN == 128) ? true : (tid < 128);

    float acc[TM][TN];
    #pragma unroll
    for (int i = 0; i < TM; i++)
        #pragma unroll
        for (int j = 0; j < TN; j++) acc[i][j] = 0.0f;

    float4 av = make_float4(0.f, 0.f, 0.f, 0.f);
    if (gA < M) {
        av = *(const float4*)&A[(size_t)gA * K + ac4];
        if constexpr (ABR) {
            av.x = fmaxf(av.x + abias[ac4 + 0], 0.f);
            av.y = fmaxf(av.y + abias[ac4 + 1], 0.f);
            av.z = fmaxf(av.z + abias[ac4 + 2], 0.f);
            av.w = fmaxf(av.w + abias[ac4 + 3], 0.f);
        }
    }
    float4 bv = make_float4(0.f, 0.f, 0.f, 0.f);
    if (bactive) bv = *(const float4*)&B[(size_t)brow * N + col0 + bc4];

    for (int k0 = 0; k0 < K; k0 += BK) {
        As[ac4 + 0][arow] = av.x;
        As[ac4 + 1][arow] = av.y;
        As[ac4 + 2][arow] = av.z;
        As[ac4 + 3][arow] = av.w;
        if (bactive) *(float4*)&Bs[brow][bc4] = bv;
        __syncthreads();

        if (k0 + BK < K) {
            av = make_float4(0.f, 0.f, 0.f, 0.f);
            if (gA < M) {
                av = *(const float4*)&A[(size_t)gA * K + (k0 + BK) + ac4];
                if constexpr (ABR) {
                    av.x = fmaxf(av.x + abias[k0 + BK + ac4 + 0], 0.f);
                    av.y = fmaxf(av.y + abias[k0 + BK + ac4 + 1], 0.f);
                    av.z = fmaxf(av.z + abias[k0 + BK + ac4 + 2], 0.f);
                    av.w = fmaxf(av.w + abias[k0 + BK + ac4 + 3], 0.f);
                }
            }
            if (bactive) bv = *(const float4*)&B[(size_t)(k0 + BK + brow) * N + col0 + bc4];
        }

        #pragma unroll
        for (int k = 0; k < BK; k++) {
            float a[TM], b[TN];
            #pragma unroll
            for (int q = 0; q < TM / 4; q++)
                *(float4*)&a[q * 4] = *(const float4*)&As[k][ty * TM + q * 4];
            #pragma unroll
            for (int q = 0; q < TN / 4; q++)
                *(float4*)&b[q * 4] = *(const float4*)&Bs[k][tx * TN + q * 4];
            #pragma unroll
            for (int i = 0; i < TM; i++)
                #pragma unroll
                for (int j = 0; j < TN; j++)
                    acc[i][j] += a[i] * b[j];
        }
        __syncthreads();
    }

    #pragma unroll
    for (int i = 0; i < TM; i++) {
        int r = row0 + ty * TM + i;
        if (r >= M) continue;
        #pragma unroll
        for (int j = 0; j < TN; j += 4) {
            int c = col0 + tx * TN + j;
            float4 v = *(float4*)&acc[i][j];
            if constexpr (USE_BIAS) {
                v.x += bias[c + 0]; v.y += bias[c + 1];
                v.z += bias[c + 2]; v.w += bias[c + 3];
            }
            if constexpr (DO_RELU) {
                v.x = fmaxf(v.x, 0.f); v.y = fmaxf(v.y, 0.f);
                v.z = fmaxf(v.z, 0.f); v.w = fmaxf(v.w, 0.f);
            }
            *(float4*)&C[(size_t)r * N + c] = v;
        }
    }
}

// ---------------- aggregation (float4; 128 threads; 4-edge unroll, 2 accumulators) ----------------
template<int D, int OSEL, int PRESCALE>
__global__ __launch_bounds__(128)
void agg4_kernel(float* __restrict__ outExt, const float* __restrict__ bias)
{
    constexpr int TPN = D / 4;
    constexpr int NPB = 128 / TPN;
    float* out;
    if constexpr (OSEL == 1) out = g_hcur;
    else out = outExt;

    const int lane = threadIdx.x % TPN;
    const int node = blockIdx.x * NPB + threadIdx.x / TPN;
    if (node >= N_NODES) return;

    const int s = g_row_ptr[node];
    const int e = g_row_ptr[node + 1];
    const float4* __restrict__ hp = (const float4*)g_hpre;
    const int* __restrict__ csr = g_csr_src;

    float4 acc0 = make_float4(0.f, 0.f, 0.f, 0.f);
    float4 acc1 = make_float4(0.f, 0.f, 0.f, 0.f);
    int i = s;
    for (; i + 3 < e; i += 4) {
        int s0 = csr[i];
        int s1 = csr[i + 1];
        int s2 = csr[i + 2];
        int s3 = csr[i + 3];
        float4 v0 = hp[(size_t)s0 * TPN + lane];
        float4 v1 = hp[(size_t)s1 * TPN + lane];
        float4 v2 = hp[(size_t)s2 * TPN + lane];
        float4 v3 = hp[(size_t)s3 * TPN + lane];
        acc0.x += v0.x; acc0.y += v0.y; acc0.z += v0.z; acc0.w += v0.w;
        acc1.x += v1.x; acc1.y += v1.y; acc1.z += v1.z; acc1.w += v1.w;
        acc0.x += v2.x; acc0.y += v2.y; acc0.z += v2.z; acc0.w += v2.w;
        acc1.x += v3.x; acc1.y += v3.y; acc1.z += v3.z; acc1.w += v3.w;
    }
    for (; i < e; i++) {
        int s0 = csr[i];
        float4 v0 = hp[(size_t)s0 * TPN + lane];
        acc0.x += v0.x; acc0.y += v0.y; acc0.z += v0.z; acc0.w += v0.w;
    }
    acc0.x += acc1.x; acc0.y += acc1.y; acc0.z += acc1.z; acc0.w += acc1.w;

    const float sc = g_deg_in_inv[node];
    float osc = 1.0f;
    if constexpr (PRESCALE) osc = g_deg_out_inv[node];
    float4 bb = *(const float4*)&bias[lane * 4];
    float4 r;
    r.x = fmaxf(acc0.x * sc + bb.x, 0.f) * osc;
    r.y = fmaxf(acc0.y * sc + bb.y, 0.f) * osc;
    r.z = fmaxf(acc0.z * sc + bb.z, 0.f) * osc;
    r.w = fmaxf(acc0.w * sc + bb.w, 0.f) * osc;
    *(float4*)&out[(size_t)node * D + lane * 4] = r;
}

// ---------------- launch ----------------
extern "C" void kernel_launch(void* const* d_in, const int* in_sizes, int n_in,
                              void* d_out, int out_size)
{
    const float* x   = (const float*)d_in[0];
    const int*   ei  = (const int*)d_in[1];
    const float* W1  = (const float*)d_in[2];
    const float* b1  = (const float*)d_in[3];
    const float* W2  = (const float*)d_in[4];
    const float* b2  = (const float*)d_in[5];
    const float* W3  = (const float*)d_in[6];
    const float* b3  = (const float*)d_in[7];
    const float* mW1 = (const float*)d_in[8];
    const float* mb1 = (const float*)d_in[9];
    const float* mW2 = (const float*)d_in[10];
    const float* mb2 = (const float*)d_in[11];

    const int N = in_sizes[0] / D_IN;       // 50000
    const int E = in_sizes[1] / 2;          // 800000

    float* out      = (float*)d_out;
    float* h_last   = (float*)d_out + (size_t)N * D_OUT;

    const int T = 256;
    const int nbN = (N + T - 1) / T;
    const int nbE = (E + T - 1) / T;
    const int nbScan = (N + 1023) / 1024;
    const int tfRows = (N + 127) / 128;     // 391

    // ---- degrees (needed by layer-1 GEMM) ----
    zero_counts_kernel<<<nbN, T>>>(N);
    degree_kernel<<<nbE, T>>>(ei, E);
    inv_kernel<<<nbN, T>>>(N);

    // ---- layer-1 GEMM (wide-tile experiment; 4th launch -> ncu-profiled) ----
    {
        dim3 grid(1, tfRows);
        gemm_tf32_w256<0, 1, 1><<<grid, 512>>>(x, W1, N, D_IN);
    }

    // ---- CSR build (independent of GEMM; must finish before agg1) ----
    scan1_kernel<<<nbScan, 1024>>>(N);
    scan2_kernel<<<1, 32>>>(nbScan);
    scan3_kernel<<<nbScan, 1024>>>(N);
    copy_fill_kernel<<<nbN, T>>>(N);
    fill_csr_kernel<<<nbE, T>>>(ei, E);

    // ---- layer 1 aggregation ----
    agg4_kernel<D_HID2, 1, 1><<<(N + 1) / 2, 128>>>(nullptr, b1);

    // ---- layer 2 (wide-tile experiment) ----
    {
        dim3 grid(1, tfRows);
        gemm_tf32_w256<1, 1, 0><<<grid, 512>>>(nullptr, W2, N, D_HID2);
        agg4_kernel<D_HID2, 1, 1><<<(N + 1) / 2, 128>>>(nullptr, b2);
    }
    // ---- layer 3: R13-proven 512-thread BN=128 kernel; h_last into d_out ----
    {
        dim3 grid(D_HID / 128, tfRows);
        gemm_tf32_512<1, 1, 0><<<grid, 512>>>(nullptr, W3, N, D_HID, D_HID2);
        agg4_kernel<D_HID, 0, 0><<<(N + 3) / 4, 128>>>(h_last, b3);
    }
    // ---- MLP layer 1 (tf32, raw GEMM into scratch) ----
    {
        dim3 grid(1, tfRows);
        gemm_tf32_kernel<64, 0, 2, 0><<<grid, 256>>>(h_last, mW1, N, D_MLP, D_HID);
    }
    // ---- MLP layer 2 (SIMT, A-side relu(a+mb1), guarded d_out store) ----
    {
        dim3 grid(D_OUT / 64, tfRows);
        gemm128_kernel<64, 2, 0, 1, 0, 1><<<grid, GTHREADS>>>(nullptr, mW2, out,
                                                              N, D_OUT, D_MLP, mb2, mb1);
    }
}

// round 15
// speedup vs baseline: 1.5996x; 1.0434x over previous
#include <cuda_runtime.h>
#include <cuda_bf16.h>
#include <mma.h>
#include <cstdint>

using namespace nvcuda;

#define N_NODES 50000
#define N_PAD   50048
#define N_EDGES 800000
#define D_IN    256
#define D_HID2  256
#define D_HID   128
#define D_MLP   64
#define D_OUT   64

// ---------------- scratch ----------------
__device__ float g_hpre[(size_t)N_PAD * D_HID2];
__device__ float g_hcur[(size_t)N_PAD * D_HID2];
__device__ float g_hidden[(size_t)N_PAD * D_MLP];
__device__ float g_deg_out_inv[N_NODES];
__device__ float g_deg_in_inv[N_NODES];
__device__ int   g_deg_out_cnt[N_NODES];
__device__ int   g_deg_in_cnt[N_NODES];
__device__ int   g_row_ptr[N_NODES + 1];
__device__ int   g_fill_ptr[N_NODES];
__device__ int   g_blk[64];
__device__ int   g_csr_src[N_EDGES];

template<int SEL>
__device__ __forceinline__ const float* select_in(const float* ext) {
    if constexpr (SEL == 1) return g_hcur;
    else if constexpr (SEL == 2) return g_hidden;
    else return ext;
}
template<int SEL>
__device__ __forceinline__ float* select_out(float* ext) {
    if constexpr (SEL == 1) return g_hpre;
    else if constexpr (SEL == 2) return g_hidden;
    else return ext;
}

// ---------------- degree / CSR ----------------

__global__ void zero_counts_kernel(int n) {
    int i = blockIdx.x * blockDim.x + threadIdx.x;
    if (i < n) { g_deg_out_cnt[i] = 0; g_deg_in_cnt[i] = 0; }
}

__global__ void degree_kernel(const int* __restrict__ ei, int E) {
    int e = blockIdx.x * blockDim.x + threadIdx.x;
    if (e < E) {
        atomicAdd(&g_deg_out_cnt[ei[e]], 1);
        atomicAdd(&g_deg_in_cnt[ei[E + e]], 1);
    }
}

__global__ void inv_kernel(int n) {
    int i = blockIdx.x * blockDim.x + threadIdx.x;
    if (i < n) {
        g_deg_out_inv[i] = rsqrtf(fmaxf((float)g_deg_out_cnt[i], 1.0f));
        g_deg_in_inv[i]  = rsqrtf(fmaxf((float)g_deg_in_cnt[i], 1.0f));
    }
}

__global__ void scan1_kernel(int n) {
    __shared__ int s[1024];
    int tid = threadIdx.x;
    int i = blockIdx.x * 1024 + tid;
    int v = (i < n) ? g_deg_in_cnt[i] : 0;
    s[tid] = v;
    __syncthreads();
    #pragma unroll
    for (int off = 1; off < 1024; off <<= 1) {
        int t = 0;
        if (tid >= off) t = s[tid - off];
        __syncthreads();
        s[tid] += t;
        __syncthreads();
    }
    if (i < n) g_row_ptr[i + 1] = s[tid];
    if (tid == 1023) g_blk[blockIdx.x] = s[1023];
}

__global__ void scan2_kernel(int nb) {
    if (threadIdx.x == 0 && blockIdx.x == 0) {
        int acc = 0;
        for (int i = 0; i < nb; i++) { int t = g_blk[i]; g_blk[i] = acc; acc += t; }
    }
}

__global__ void scan3_kernel(int n) {
    int i = blockIdx.x * 1024 + threadIdx.x;
    if (i < n) g_row_ptr[i + 1] += g_blk[blockIdx.x];
    if (i == 0) g_row_ptr[0] = 0;
}

__global__ void copy_fill_kernel(int n) {
    int i = blockIdx.x * blockDim.x + threadIdx.x;
    if (i < n) g_fill_ptr[i] = g_row_ptr[i];
}

__global__ void fill_csr_kernel(const int* __restrict__ ei, int E) {
    int e = blockIdx.x * blockDim.x + threadIdx.x;
    if (e < E) {
        int d = ei[E + e];
        int pos = atomicAdd(&g_fill_ptr[d], 1);
        g_csr_src[pos] = ei[e];
    }
}

// ---------------- tf32 WMMA GEMM, wide tile: BM=128 x BN=256 x BK=16, 512 thr ----------------
template<int ASEL, int CSEL, int RS>
__global__ __launch_bounds__(512)
void gemm_tf32_w256(const float* __restrict__ Aext, const float* __restrict__ B,
                    int M, int K)
{
    constexpr int N = 256;
    constexpr int BM = 128, BN = 256, BK = 16;
    constexpr int LDA = BK + 8;      // 24
    constexpr int LDB = BN + 8;      // 264

    const float* A = select_in<ASEL>(Aext);
    float* C = select_out<CSEL>(nullptr);

    __shared__ float As[BM][LDA];
    __shared__ float Bs[BK][LDB];

    const int tid  = threadIdx.x;
    const int warp = tid >> 5;
    const int wr   = warp >> 2;
    const int wc   = warp & 3;
    const int row0 = blockIdx.y * BM;

    wmma::fragment<wmma::accumulator, 16, 16, 8, float> acc[2][4];
    #pragma unroll
    for (int i = 0; i < 2; i++)
        #pragma unroll
        for (int j = 0; j < 4; j++) wmma::fill_fragment(acc[i][j], 0.0f);

    const int ar = tid >> 2;
    const int ac4 = (tid & 3) << 2;
    float4 aP, bP[2];

    {
        int gr = row0 + ar;
        float4 v = make_float4(0.f, 0.f, 0.f, 0.f);
        if (gr < M) {
            v = *(const float4*)&A[(size_t)gr * K + ac4];
            if constexpr (RS) {
                float sc = g_deg_out_inv[gr];
                v.x *= sc; v.y *= sc; v.z *= sc; v.w *= sc;
            }
        }
        aP = v;
    }
    #pragma unroll
    for (int l = 0; l < 2; l++) {
        int lin = tid + l * 512;
        int r = lin >> 6, c4 = (lin & 63) << 2;
        bP[l] = *(const float4*)&B[(size_t)r * N + c4];
    }

    for (int k0 = 0; k0 < K; k0 += BK) {
        As[ar][ac4 + 0] = wmma::__float_to_tf32(aP.x);
        As[ar][ac4 + 1] = wmma::__float_to_tf32(aP.y);
        As[ar][ac4 + 2] = wmma::__float_to_tf32(aP.z);
        As[ar][ac4 + 3] = wmma::__float_to_tf32(aP.w);
        #pragma unroll
        for (int l = 0; l < 2; l++) {
            int lin = tid + l * 512;
            int r = lin >> 6, c4 = (lin & 63) << 2;
            Bs[r][c4 + 0] = wmma::__float_to_tf32(bP[l].x);
            Bs[r][c4 + 1] = wmma::__float_to_tf32(bP[l].y);
            Bs[r][c4 + 2] = wmma::__float_to_tf32(bP[l].z);
            Bs[r][c4 + 3] = wmma::__float_to_tf32(bP[l].w);
        }
        __syncthreads();

        if (k0 + BK < K) {
            int gr = row0 + ar;
            float4 v = make_float4(0.f, 0.f, 0.f, 0.f);
            if (gr < M) {
                v = *(const float4*)&A[(size_t)gr * K + (k0 + BK) + ac4];
                if constexpr (RS) {
                    float sc = g_deg_out_inv[gr];
                    v.x *= sc; v.y *= sc; v.z *= sc; v.w *= sc;
                }
            }
            aP = v;
            #pragma unroll
            for (int l = 0; l < 2; l++) {
                int lin = tid + l * 512;
                int r = lin >> 6, c4 = (lin & 63) << 2;
                bP[l] = *(const float4*)&B[(size_t)(k0 + BK + r) * N + c4];
            }
        }

        #pragma unroll
        for (int kk = 0; kk < BK; kk += 8) {
            wmma::fragment<wmma::matrix_a, 16, 16, 8, wmma::precision::tf32, wmma::row_major> af[2];
            #pragma unroll
            for (int i = 0; i < 2; i++)
                wmma::load_matrix_sync(af[i], &As[wr * 32 + i * 16][kk], LDA);
            wmma::fragment<wmma::matrix_b, 16, 16, 8, wmma::precision::tf32, wmma::row_major> bf[4];
            #pragma unroll
            for (int j = 0; j < 4; j++)
                wmma::load_matrix_sync(bf[j], &Bs[kk][wc * 64 + j * 16], LDB);
            #pragma unroll
            for (int i = 0; i < 2; i++)
                #pragma unroll
                for (int j = 0; j < 4; j++)
                    wmma::mma_sync(acc[i][j], af[i], bf[j], acc[i][j]);
        }
        __syncthreads();
    }

    #pragma unroll
    for (int i = 0; i < 2; i++)
        #pragma unroll
        for (int j = 0; j < 4; j++) {
            int r = row0 + wr * 32 + i * 16;
            int c = wc * 64 + j * 16;
            wmma::store_matrix_sync(&C[(size_t)r * N + c], acc[i][j], N, wmma::mem_row_major);
        }
}

// ---------------- tf32 WMMA GEMM, 512 threads / 16 warps (R13-proven, BN=128) ----------------
template<int ASEL, int CSEL, int RS>
__global__ __launch_bounds__(512)
void gemm_tf32_512(const float* __restrict__ Aext, const float* __restrict__ B,
                   int M, int N, int K)
{
    constexpr int BM = 128, BN = 128, BK = 32;
    constexpr int LDA = BK + 8;
    constexpr int LDB = BN + 8;

    const float* A = select_in<ASEL>(Aext);
    float* C = select_out<CSEL>(nullptr);

    __shared__ float As[BM][LDA];
    __shared__ float Bs[BK][LDB];

    const int tid  = threadIdx.x;
    const int warp = tid >> 5;
    const int wr   = warp >> 2;
    const int wc   = warp & 3;
    const int row0 = blockIdx.y * BM;
    const int col0 = blockIdx.x * BN;

    wmma::fragment<wmma::accumulator, 16, 16, 8, float> acc[2][2];
    #pragma unroll
    for (int i = 0; i < 2; i++)
        #pragma unroll
        for (int j = 0; j < 2; j++) wmma::fill_fragment(acc[i][j], 0.0f);

    float4 aP[2], bP[2];
    #pragma unroll
    for (int l = 0; l < 2; l++) {
        int lin = tid + l * 512;
        int r = lin >> 3, c4 = (lin & 7) << 2;
        int gr = row0 + r;
        float4 v = make_float4(0.f, 0.f, 0.f, 0.f);
        if (gr < M) {
            v = *(const float4*)&A[(size_t)gr * K + c4];
            if constexpr (RS) {
                float sc = g_deg_out_inv[gr];
                v.x *= sc; v.y *= sc; v.z *= sc; v.w *= sc;
            }
        }
        aP[l] = v;
    }
    #pragma unroll
    for (int l = 0; l < 2; l++) {
        int lin = tid + l * 512;
        int r = lin >> 5, c4 = (lin & 31) << 2;
        bP[l] = *(const float4*)&B[(size_t)r * N + col0 + c4];
    }

    for (int k0 = 0; k0 < K; k0 += BK) {
        #pragma unroll
        for (int l = 0; l < 2; l++) {
            int lin = tid + l * 512;
            int r = lin >> 3, c4 = (lin & 7) << 2;
            As[r][c4 + 0] = wmma::__float_to_tf32(aP[l].x);
            As[r][c4 + 1] = wmma::__float_to_tf32(aP[l].y);
            As[r][c4 + 2] = wmma::__float_to_tf32(aP[l].z);
            As[r][c4 + 3] = wmma::__float_to_tf32(aP[l].w);
        }
        #pragma unroll
        for (int l = 0; l < 2; l++) {
            int lin = tid + l * 512;
            int r = lin >> 5, c4 = (lin & 31) << 2;
            Bs[r][c4 + 0] = wmma::__float_to_tf32(bP[l].x);
            Bs[r][c4 + 1] = wmma::__float_to_tf32(bP[l].y);
            Bs[r][c4 + 2] = wmma::__float_to_tf32(bP[l].z);
            Bs[r][c4 + 3] = wmma::__float_to_tf32(bP[l].w);
        }
        __syncthreads();

        if (k0 + BK < K) {
            #pragma unroll
            for (int l = 0; l < 2; l++) {
                int lin = tid + l * 512;
                int r = lin >> 3, c4 = (lin & 7) << 2;
                int gr = row0 + r;
                float4 v = make_float4(0.f, 0.f, 0.f, 0.f);
                if (gr < M) {
                    v = *(const float4*)&A[(size_t)gr * K + (k0 + BK) + c4];
                    if constexpr (RS) {
                        float sc = g_deg_out_inv[gr];
                        v.x *= sc; v.y *= sc; v.z *= sc; v.w *= sc;
                    }
                }
                aP[l] = v;
            }
            #pragma unroll
            for (int l = 0; l < 2; l++) {
                int lin = tid + l * 512;
                int r = lin >> 5, c4 = (lin & 31) << 2;
                bP[l] = *(const float4*)&B[(size_t)(k0 + BK + r) * N + col0 + c4];
            }
        }

        #pragma unroll
        for (int kk = 0; kk < BK; kk += 8) {
            wmma::fragment<wmma::matrix_a, 16, 16, 8, wmma::precision::tf32, wmma::row_major> af[2];
            #pragma unroll
            for (int i = 0; i < 2; i++)
                wmma::load_matrix_sync(af[i], &As[wr * 32 + i * 16][kk], LDA);
            wmma::fragment<wmma::matrix_b, 16, 16, 8, wmma::precision::tf32, wmma::row_major> bf[2];
            #pragma unroll
            for (int j = 0; j < 2; j++)
                wmma::load_matrix_sync(bf[j], &Bs[kk][wc * 32 + j * 16], LDB);
            #pragma unroll
            for (int i = 0; i < 2; i++)
                #pragma unroll
                for (int j = 0; j < 2; j++)
                    wmma::mma_sync(acc[i][j], af[i], bf[j], acc[i][j]);
        }
        __syncthreads();
    }

    #pragma unroll
    for (int i = 0; i < 2; i++)
        #pragma unroll
        for (int j = 0; j < 2; j++) {
            int r = row0 + wr * 32 + i * 16;
            int c = col0 + wc * 32 + j * 16;
            wmma::store_matrix_sync(&C[(size_t)r * N + c], acc[i][j], N, wmma::mem_row_major);
        }
}

// ---------------- tf32 WMMA GEMM (256 threads; MLP1 BN=64) ----------------
template<int BN, int ASEL, int CSEL, int RS>
__global__ __launch_bounds__(256)
void gemm_tf32_kernel(const float* __restrict__ Aext, const float* __restrict__ B,
                      int M, int N, int K)
{
    constexpr int BM = 128, BK = 32;
    constexpr int LDA = BK + 8;
    constexpr int LDB = BN + 8;
    constexpr int WN  = BN / 2;
    constexpr int NF  = WN / 16;
    constexpr int BL  = BN / 32;
    constexpr int BC4 = BN / 4;

    const float* A = select_in<ASEL>(Aext);
    float* C = select_out<CSEL>(nullptr);

    __shared__ float As[BM][LDA];
    __shared__ float Bs[BK][LDB];

    const int tid  = threadIdx.x;
    const int warp = tid >> 5;
    const int wr   = warp >> 1;
    const int wc   = warp & 1;
    const int row0 = blockIdx.y * BM;
    const int col0 = blockIdx.x * BN;

    wmma::fragment<wmma::accumulator, 16, 16, 8, float> acc[2][NF];
    #pragma unroll
    for (int i = 0; i < 2; i++)
        #pragma unroll
        for (int j = 0; j < NF; j++) wmma::fill_fragment(acc[i][j], 0.0f);

    float4 aP[4], bP[BL];
    #pragma unroll
    for (int l = 0; l < 4; l++) {
        int lin = tid + l * 256;
        int r = lin >> 3, c4 = (lin & 7) << 2;
        int gr = row0 + r;
        float4 v = make_float4(0.f, 0.f, 0.f, 0.f);
        if (gr < M) {
            v = *(const float4*)&A[(size_t)gr * K + c4];
            if constexpr (RS) {
                float sc = g_deg_out_inv[gr];
                v.x *= sc; v.y *= sc; v.z *= sc; v.w *= sc;
            }
        }
        aP[l] = v;
    }
    #pragma unroll
    for (int l = 0; l < BL; l++) {
        int lin = tid + l * 256;
        int r = lin / BC4, c4 = (lin % BC4) * 4;
        bP[l] = *(const float4*)&B[(size_t)r * N + col0 + c4];
    }

    for (int k0 = 0; k0 < K; k0 += BK) {
        #pragma unroll
        for (int l = 0; l < 4; l++) {
            int lin = tid + l * 256;
            int r = lin >> 3, c4 = (lin & 7) << 2;
            As[r][c4 + 0] = wmma::__float_to_tf32(aP[l].x);
            As[r][c4 + 1] = wmma::__float_to_tf32(aP[l].y);
            As[r][c4 + 2] = wmma::__float_to_tf32(aP[l].z);
            As[r][c4 + 3] = wmma::__float_to_tf32(aP[l].w);
        }
        #pragma unroll
        for (int l = 0; l < BL; l++) {
            int lin = tid + l * 256;
            int r = lin / BC4, c4 = (lin % BC4) * 4;
            Bs[r][c4 + 0] = wmma::__float_to_tf32(bP[l].x);
            Bs[r][c4 + 1] = wmma::__float_to_tf32(bP[l].y);
            Bs[r][c4 + 2] = wmma::__float_to_tf32(bP[l].z);
            Bs[r][c4 + 3] = wmma::__float_to_tf32(bP[l].w);
        }
        __syncthreads();

        if (k0 + BK < K) {
            #pragma unroll
            for (int l = 0; l < 4; l++) {
                int lin = tid + l * 256;
                int r = lin >> 3, c4 = (lin & 7) << 2;
                int gr = row0 + r;
                float4 v = make_float4(0.f, 0.f, 0.f, 0.f);
                if (gr < M) {
                    v = *(const float4*)&A[(size_t)gr * K + (k0 + BK) + c4];
                    if constexpr (RS) {
                        float sc = g_deg_out_inv[gr];
                        v.x *= sc; v.y *= sc; v.z *= sc; v.w *= sc;
                    }
                }
                aP[l] = v;
            }
            #pragma unroll
            for (int l = 0; l < BL; l++) {
                int lin = tid + l * 256;
                int r = lin / BC4, c4 = (lin % BC4) * 4;
                bP[l] = *(const float4*)&B[(size_t)(k0 + BK + r) * N + col0 + c4];
            }
        }

        #pragma unroll
        for (int kk = 0; kk < BK; kk += 8) {
            wmma::fragment<wmma::matrix_a, 16, 16, 8, wmma::precision::tf32, wmma::row_major> af[2];
            #pragma unroll
            for (int i = 0; i < 2; i++)
                wmma::load_matrix_sync(af[i], &As[wr * 32 + i * 16][kk], LDA);
            wmma::fragment<wmma::matrix_b, 16, 16, 8, wmma::precision::tf32, wmma::row_major> bf[NF];
            #pragma unroll
            for (int j = 0; j < NF; j++)
                wmma::load_matrix_sync(bf[j], &Bs[kk][wc * WN + j * 16], LDB);
            #pragma unroll
            for (int i = 0; i < 2; i++)
                #pragma unroll
                for (int j = 0; j < NF; j++)
                    wmma::mma_sync(acc[i][j], af[i], bf[j], acc[i][j]);
        }
        __syncthreads();
    }

    #pragma unroll
    for (int i = 0; i < 2; i++)
        #pragma unroll
        for (int j = 0; j < NF; j++) {
            int r = row0 + wr * 32 + i * 16;
            int c = col0 + wc * WN + j * 16;
            wmma::store_matrix_sync(&C[(size_t)r * N + c], acc[i][j], N, wmma::mem_row_major);
        }
}

// ---------------- SIMT GEMM (final MLP layer; guarded d_out store) ----------------
#define GTHREADS 256
template<int BN, int ASEL, int CSEL, int USE_BIAS, int DO_RELU, int ABR>
__global__ __launch_bounds__(GTHREADS)
void gemm128_kernel(const float* __restrict__ Aext, const float* __restrict__ B,
                    float* __restrict__ Cext, int M, int N, int K,
                    const float* __restrict__ bias, const float* __restrict__ abias)
{
    constexpr int BM = 128;
    constexpr int BK = 8;
    constexpr int TM = 8;
    constexpr int TN = BN / 16;

    const float* A = select_in<ASEL>(Aext);
    float* C = select_out<CSEL>(Cext);

    __shared__ float As[BK][BM + 4];
    __shared__ float Bs[BK][BN];

    const int tid = threadIdx.x;
    const int tx = tid % 16;
    const int ty = tid / 16;
    const int row0 = blockIdx.y * BM;
    const int col0 = blockIdx.x * BN;

    const int arow = tid / 2;
    const int ac4  = (tid % 2) * 4;
    const int gA   = row0 + arow;

    const int brow = (BN == 128) ? (tid / 32) : (tid / 16);
    const int bc4  = (BN == 128) ? ((tid % 32) * 4) : ((tid % 16) * 4);
    const bool bactive = (BN == 128) ? true : (tid < 128);

    float acc[TM][TN];
    #pragma unroll
    for (int i = 0; i < TM; i++)
        #pragma unroll
        for (int j = 0; j < TN; j++) acc[i][j] = 0.0f;

    float4 av = make_float4(0.f, 0.f, 0.f, 0.f);
    if (gA < M) {
        av = *(const float4*)&A[(size_t)gA * K + ac4];
        if constexpr (ABR) {
            av.x = fmaxf(av.x + abias[ac4 + 0], 0.f);
            av.y = fmaxf(av.y + abias[ac4 + 1], 0.f);
            av.z = fmaxf(av.z + abias[ac4 + 2], 0.f);
            av.w = fmaxf(av.w + abias[ac4 + 3], 0.f);
        }
    }
    float4 bv = make_float4(0.f, 0.f, 0.f, 0.f);
    if (bactive) bv = *(const float4*)&B[(size_t)brow * N + col0 + bc4];

    for (int k0 = 0; k0 < K; k0 += BK) {
        As[ac4 + 0][arow] = av.x;
        As[ac4 + 1][arow] = av.y;
        As[ac4 + 2][arow] = av.z;
        As[ac4 + 3][arow] = av.w;
        if (bactive) *(float4*)&Bs[brow][bc4] = bv;
        __syncthreads();

        if (k0 + BK < K) {
            av = make_float4(0.f, 0.f, 0.f, 0.f);
            if (gA < M) {
                av = *(const float4*)&A[(size_t)gA * K + (k0 + BK) + ac4];
                if constexpr (ABR) {
                    av.x = fmaxf(av.x + abias[k0 + BK + ac4 + 0], 0.f);
                    av.y = fmaxf(av.y + abias[k0 + BK + ac4 + 1], 0.f);
                    av.z = fmaxf(av.z + abias[k0 + BK + ac4 + 2], 0.f);
                    av.w = fmaxf(av.w + abias[k0 + BK + ac4 + 3], 0.f);
                }
            }
            if (bactive) bv = *(const float4*)&B[(size_t)(k0 + BK + brow) * N + col0 + bc4];
        }

        #pragma unroll
        for (int k = 0; k < BK; k++) {
            float a[TM], b[TN];
            #pragma unroll
            for (int q = 0; q < TM / 4; q++)
                *(float4*)&a[q * 4] = *(const float4*)&As[k][ty * TM + q * 4];
            #pragma unroll
            for (int q = 0; q < TN / 4; q++)
                *(float4*)&b[q * 4] = *(const float4*)&Bs[k][tx * TN + q * 4];
            #pragma unroll
            for (int i = 0; i < TM; i++)
                #pragma unroll
                for (int j = 0; j < TN; j++)
                    acc[i][j] += a[i] * b[j];
        }
        __syncthreads();
    }

    #pragma unroll
    for (int i = 0; i < TM; i++) {
        int r = row0 + ty * TM + i;
        if (r >= M) continue;
        #pragma unroll
        for (int j = 0; j < TN; j += 4) {
            int c = col0 + tx * TN + j;
            float4 v = *(float4*)&acc[i][j];
            if constexpr (USE_BIAS) {
                v.x += bias[c + 0]; v.y += bias[c + 1];
                v.z += bias[c + 2]; v.w += bias[c + 3];
            }
            if constexpr (DO_RELU) {
                v.x = fmaxf(v.x, 0.f); v.y = fmaxf(v.y, 0.f);
                v.z = fmaxf(v.z, 0.f); v.w = fmaxf(v.w, 0.f);
            }
            *(float4*)&C[(size_t)r * N + c] = v;
        }
    }
}

// ---------------- aggregation (float4; 128 threads; 4-edge unroll, 2 accumulators) ----------------
template<int D, int OSEL, int PRESCALE>
__global__ __launch_bounds__(128)
void agg4_kernel(float* __restrict__ outExt, const float* __restrict__ bias)
{
    constexpr int TPN = D / 4;
    constexpr int NPB = 128 / TPN;
    float* out;
    if constexpr (OSEL == 1) out = g_hcur;
    else out = outExt;

    const int lane = threadIdx.x % TPN;
    const int node = blockIdx.x * NPB + threadIdx.x / TPN;
    if (node >= N_NODES) return;

    const int s = g_row_ptr[node];
    const int e = g_row_ptr[node + 1];
    const float4* __restrict__ hp = (const float4*)g_hpre;
    const int* __restrict__ csr = g_csr_src;

    float4 acc0 = make_float4(0.f, 0.f, 0.f, 0.f);
    float4 acc1 = make_float4(0.f, 0.f, 0.f, 0.f);
    int i = s;
    for (; i + 3 < e; i += 4) {
        int s0 = csr[i];
        int s1 = csr[i + 1];
        int s2 = csr[i + 2];
        int s3 = csr[i + 3];
        float4 v0 = hp[(size_t)s0 * TPN + lane];
        float4 v1 = hp[(size_t)s1 * TPN + lane];
        float4 v2 = hp[(size_t)s2 * TPN + lane];
        float4 v3 = hp[(size_t)s3 * TPN + lane];
        acc0.x += v0.x; acc0.y += v0.y; acc0.z += v0.z; acc0.w += v0.w;
        acc1.x += v1.x; acc1.y += v1.y; acc1.z += v1.z; acc1.w += v1.w;
        acc0.x += v2.x; acc0.y += v2.y; acc0.z += v2.z; acc0.w += v2.w;
        acc1.x += v3.x; acc1.y += v3.y; acc1.z += v3.z; acc1.w += v3.w;
    }
    for (; i < e; i++) {
        int s0 = csr[i];
        float4 v0 = hp[(size_t)s0 * TPN + lane];
        acc0.x += v0.x; acc0.y += v0.y; acc0.z += v0.z; acc0.w += v0.w;
    }
    acc0.x += acc1.x; acc0.y += acc1.y; acc0.z += acc1.z; acc0.w += acc1.w;

    const float sc = g_deg_in_inv[node];
    float osc = 1.0f;
    if constexpr (PRESCALE) osc = g_deg_out_inv[node];
    float4 bb = *(const float4*)&bias[lane * 4];
    float4 r;
    r.x = fmaxf(acc0.x * sc + bb.x, 0.f) * osc;
    r.y = fmaxf(acc0.y * sc + bb.y, 0.f) * osc;
    r.z = fmaxf(acc0.z * sc + bb.z, 0.f) * osc;
    r.w = fmaxf(acc0.w * sc + bb.w, 0.f) * osc;
    *(float4*)&out[(size_t)node * D + lane * 4] = r;
}

// ---------------- launch ----------------
extern "C" void kernel_launch(void* const* d_in, const int* in_sizes, int n_in,
                              void* d_out, int out_size)
{
    const float* x   = (const float*)d_in[0];
    const int*   ei  = (const int*)d_in[1];
    const float* W1  = (const float*)d_in[2];
    const float* b1  = (const float*)d_in[3];
    const float* W2  = (const float*)d_in[4];
    const float* b2  = (const float*)d_in[5];
    const float* W3  = (const float*)d_in[6];
    const float* b3  = (const float*)d_in[7];
    const float* mW1 = (const float*)d_in[8];
    const float* mb1 = (const float*)d_in[9];
    const float* mW2 = (const float*)d_in[10];
    const float* mb2 = (const float*)d_in[11];

    const int N = in_sizes[0] / D_IN;       // 50000
    const int E = in_sizes[1] / 2;          // 800000

    float* out      = (float*)d_out;
    float* h_last   = (float*)d_out + (size_t)N * D_OUT;

    const int T = 256;
    const int nbN = (N + T - 1) / T;
    const int nbE = (E + T - 1) / T;
    const int nbScan = (N + 1023) / 1024;
    const int tfRows = (N + 127) / 128;     // 391

    // side stream + events for CSR-build / GEMM overlap (created once; host-side only)
    static cudaStream_t s2 = nullptr;
    static cudaEvent_t evDeg = nullptr, evCsr = nullptr;
    if (s2 == nullptr) {
        cudaStreamCreateWithFlags(&s2, cudaStreamNonBlocking);
        cudaEventCreateWithFlags(&evDeg, cudaEventDisableTiming);
        cudaEventCreateWithFlags(&evCsr, cudaEventDisableTiming);
    }

    // ---- degrees (needed by both branches) ----
    zero_counts_kernel<<<nbN, T>>>(N);
    degree_kernel<<<nbE, T>>>(ei, E);
    inv_kernel<<<nbN, T>>>(N);
    cudaEventRecord(evDeg, 0);

    // ---- fork: CSR build on side stream (needs deg_in_cnt only) ----
    cudaStreamWaitEvent(s2, evDeg, 0);
    scan1_kernel<<<nbScan, 1024, 0, s2>>>(N);
    scan2_kernel<<<1, 32, 0, s2>>>(nbScan);
    scan3_kernel<<<nbScan, 1024, 0, s2>>>(N);
    copy_fill_kernel<<<nbN, T, 0, s2>>>(N);
    fill_csr_kernel<<<nbE, T, 0, s2>>>(ei, E);
    cudaEventRecord(evCsr, s2);

    // ---- main stream: layer-1 GEMM runs concurrently with CSR build ----
    {
        dim3 grid(1, tfRows);
        gemm_tf32_w256<0, 1, 1><<<grid, 512>>>(x, W1, N, D_IN);
    }

    // ---- join: agg1 needs both GEMM output and CSR ----
    cudaStreamWaitEvent(0, evCsr, 0);
    agg4_kernel<D_HID2, 1, 1><<<(N + 1) / 2, 128>>>(nullptr, b1);

    // ---- layer 2 ----
    {
        dim3 grid(1, tfRows);
        gemm_tf32_w256<1, 1, 0><<<grid, 512>>>(nullptr, W2, N, D_HID2);
        agg4_kernel<D_HID2, 1, 1><<<(N + 1) / 2, 128>>>(nullptr, b2);
    }
    // ---- layer 3: h_last into d_out ----
    {
        dim3 grid(D_HID / 128, tfRows);
        gemm_tf32_512<1, 1, 0><<<grid, 512>>>(nullptr, W3, N, D_HID, D_HID2);
        agg4_kernel<D_HID, 0, 0><<<(N + 3) / 4, 128>>>(h_last, b3);
    }
    // ---- MLP layer 1 (tf32, raw GEMM into scratch) ----
    {
        dim3 grid(1, tfRows);
        gemm_tf32_kernel<64, 0, 2, 0><<<grid, 256>>>(h_last, mW1, N, D_MLP, D_HID);
    }
    // ---- MLP layer 2 (SIMT, A-side relu(a+mb1), guarded d_out store) ----
    {
        dim3 grid(D_OUT / 64, tfRows);
        gemm128_kernel<64, 2, 0, 1, 0, 1><<<grid, GTHREADS>>>(nullptr, mW2, out,
                                                              N, D_OUT, D_MLP, mb2, mb1);
    }
}

// round 16
// speedup vs baseline: 1.6428x; 1.0270x over previous
#include <cuda_runtime.h>
#include <cuda_bf16.h>
#include <cuda_pipeline.h>
#include <mma.h>
#include <cstdint>

using namespace nvcuda;

#define N_NODES 50000
#define N_PAD   50048
#define N_EDGES 800000
#define D_IN    256
#define D_HID2  256
#define D_HID   128
#define D_MLP   64
#define D_OUT   64

// ---------------- scratch ----------------
__device__ float g_hpre[(size_t)N_PAD * D_HID2];
__device__ float g_hcur[(size_t)N_PAD * D_HID2];
__device__ float g_hidden[(size_t)N_PAD * D_MLP];
__device__ float g_w2r[D_HID2 * D_HID2];     // RN-tf32-rounded W2
__device__ float g_deg_out_inv[N_NODES];
__device__ float g_deg_in_inv[N_NODES];
__device__ int   g_deg_out_cnt[N_NODES];
__device__ int   g_deg_in_cnt[N_NODES];
__device__ int   g_row_ptr[N_NODES + 1];
__device__ int   g_fill_ptr[N_NODES];
__device__ int   g_blk[64];
__device__ int   g_csr_src[N_EDGES];

template<int SEL>
__device__ __forceinline__ const float* select_in(const float* ext) {
    if constexpr (SEL == 1) return g_hcur;
    else if constexpr (SEL == 2) return g_hidden;
    else return ext;
}
template<int SEL>
__device__ __forceinline__ float* select_out(float* ext) {
    if constexpr (SEL == 1) return g_hpre;
    else if constexpr (SEL == 2) return g_hidden;
    else return ext;
}

// ---------------- degree / CSR ----------------

__global__ void zero_counts_kernel(int n) {
    int i = blockIdx.x * blockDim.x + threadIdx.x;
    if (i < n) { g_deg_out_cnt[i] = 0; g_deg_in_cnt[i] = 0; }
}

__global__ void degree_kernel(const int* __restrict__ ei, int E) {
    int e = blockIdx.x * blockDim.x + threadIdx.x;
    if (e < E) {
        atomicAdd(&g_deg_out_cnt[ei[e]], 1);
        atomicAdd(&g_deg_in_cnt[ei[E + e]], 1);
    }
}

__global__ void inv_kernel(int n) {
    int i = blockIdx.x * blockDim.x + threadIdx.x;
    if (i < n) {
        g_deg_out_inv[i] = rsqrtf(fmaxf((float)g_deg_out_cnt[i], 1.0f));
        g_deg_in_inv[i]  = rsqrtf(fmaxf((float)g_deg_in_cnt[i], 1.0f));
    }
}

__global__ void scan1_kernel(int n) {
    __shared__ int s[1024];
    int tid = threadIdx.x;
    int i = blockIdx.x * 1024 + tid;
    int v = (i < n) ? g_deg_in_cnt[i] : 0;
    s[tid] = v;
    __syncthreads();
    #pragma unroll
    for (int off = 1; off < 1024; off <<= 1) {
        int t = 0;
        if (tid >= off) t = s[tid - off];
        __syncthreads();
        s[tid] += t;
        __syncthreads();
    }
    if (i < n) g_row_ptr[i + 1] = s[tid];
    if (tid == 1023) g_blk[blockIdx.x] = s[1023];
}

__global__ void scan2_kernel(int nb) {
    if (threadIdx.x == 0 && blockIdx.x == 0) {
        int acc = 0;
        for (int i = 0; i < nb; i++) { int t = g_blk[i]; g_blk[i] = acc; acc += t; }
    }
}

__global__ void scan3_kernel(int n) {
    int i = blockIdx.x * 1024 + threadIdx.x;
    if (i < n) g_row_ptr[i + 1] += g_blk[blockIdx.x];
    if (i == 0) g_row_ptr[0] = 0;
}

__global__ void copy_fill_kernel(int n) {
    int i = blockIdx.x * blockDim.x + threadIdx.x;
    if (i < n) g_fill_ptr[i] = g_row_ptr[i];
}

__global__ void fill_csr_kernel(const int* __restrict__ ei, int E) {
    int e = blockIdx.x * blockDim.x + threadIdx.x;
    if (e < E) {
        int d = ei[E + e];
        int pos = atomicAdd(&g_fill_ptr[d], 1);
        g_csr_src[pos] = ei[e];
    }
}

// RN-round W2 into scratch (side stream; needed by cp.async gemm2)
__global__ void round_w2_kernel(const float* __restrict__ w) {
    int i = blockIdx.x * blockDim.x + threadIdx.x;
    if (i < D_HID2 * D_HID2) g_w2r[i] = wmma::__float_to_tf32(w[i]);
}

// ---------------- tf32 WMMA GEMM, wide tile (register path; layer 1) ----------------
template<int ASEL, int CSEL, int RS>
__global__ __launch_bounds__(512)
void gemm_tf32_w256(const float* __restrict__ Aext, const float* __restrict__ B,
                    int M, int K)
{
    constexpr int N = 256;
    constexpr int BM = 128, BN = 256, BK = 16;
    constexpr int LDA = BK + 8;      // 24
    constexpr int LDB = BN + 8;      // 264

    const float* A = select_in<ASEL>(Aext);
    float* C = select_out<CSEL>(nullptr);

    __shared__ float As[BM][LDA];
    __shared__ float Bs[BK][LDB];

    const int tid  = threadIdx.x;
    const int warp = tid >> 5;
    const int wr   = warp >> 2;
    const int wc   = warp & 3;
    const int row0 = blockIdx.y * BM;

    wmma::fragment<wmma::accumulator, 16, 16, 8, float> acc[2][4];
    #pragma unroll
    for (int i = 0; i < 2; i++)
        #pragma unroll
        for (int j = 0; j < 4; j++) wmma::fill_fragment(acc[i][j], 0.0f);

    const int ar = tid >> 2;
    const int ac4 = (tid & 3) << 2;
    float4 aP, bP[2];

    {
        int gr = row0 + ar;
        float4 v = make_float4(0.f, 0.f, 0.f, 0.f);
        if (gr < M) {
            v = *(const float4*)&A[(size_t)gr * K + ac4];
            if constexpr (RS) {
                float sc = g_deg_out_inv[gr];
                v.x *= sc; v.y *= sc; v.z *= sc; v.w *= sc;
            }
        }
        aP = v;
    }
    #pragma unroll
    for (int l = 0; l < 2; l++) {
        int lin = tid + l * 512;
        int r = lin >> 6, c4 = (lin & 63) << 2;
        bP[l] = *(const float4*)&B[(size_t)r * N + c4];
    }

    for (int k0 = 0; k0 < K; k0 += BK) {
        As[ar][ac4 + 0] = wmma::__float_to_tf32(aP.x);
        As[ar][ac4 + 1] = wmma::__float_to_tf32(aP.y);
        As[ar][ac4 + 2] = wmma::__float_to_tf32(aP.z);
        As[ar][ac4 + 3] = wmma::__float_to_tf32(aP.w);
        #pragma unroll
        for (int l = 0; l < 2; l++) {
            int lin = tid + l * 512;
            int r = lin >> 6, c4 = (lin & 63) << 2;
            Bs[r][c4 + 0] = wmma::__float_to_tf32(bP[l].x);
            Bs[r][c4 + 1] = wmma::__float_to_tf32(bP[l].y);
            Bs[r][c4 + 2] = wmma::__float_to_tf32(bP[l].z);
            Bs[r][c4 + 3] = wmma::__float_to_tf32(bP[l].w);
        }
        __syncthreads();

        if (k0 + BK < K) {
            int gr = row0 + ar;
            float4 v = make_float4(0.f, 0.f, 0.f, 0.f);
            if (gr < M) {
                v = *(const float4*)&A[(size_t)gr * K + (k0 + BK) + ac4];
                if constexpr (RS) {
                    float sc = g_deg_out_inv[gr];
                    v.x *= sc; v.y *= sc; v.z *= sc; v.w *= sc;
                }
            }
            aP = v;
            #pragma unroll
            for (int l = 0; l < 2; l++) {
                int lin = tid + l * 512;
                int r = lin >> 6, c4 = (lin & 63) << 2;
                bP[l] = *(const float4*)&B[(size_t)(k0 + BK + r) * N + c4];
            }
        }

        #pragma unroll
        for (int kk = 0; kk < BK; kk += 8) {
            wmma::fragment<wmma::matrix_a, 16, 16, 8, wmma::precision::tf32, wmma::row_major> af[2];
            #pragma unroll
            for (int i = 0; i < 2; i++)
                wmma::load_matrix_sync(af[i], &As[wr * 32 + i * 16][kk], LDA);
            wmma::fragment<wmma::matrix_b, 16, 16, 8, wmma::precision::tf32, wmma::row_major> bf[4];
            #pragma unroll
            for (int j = 0; j < 4; j++)
                wmma::load_matrix_sync(bf[j], &Bs[kk][wc * 64 + j * 16], LDB);
            #pragma unroll
            for (int i = 0; i < 2; i++)
                #pragma unroll
                for (int j = 0; j < 4; j++)
                    wmma::mma_sync(acc[i][j], af[i], bf[j], acc[i][j]);
        }
        __syncthreads();
    }

    #pragma unroll
    for (int i = 0; i < 2; i++)
        #pragma unroll
        for (int j = 0; j < 4; j++) {
            int r = row0 + wr * 32 + i * 16;
            int c = wc * 64 + j * 16;
            wmma::store_matrix_sync(&C[(size_t)r * N + c], acc[i][j], N, wmma::mem_row_major);
        }
}

// ---------------- cp.async double-buffered tf32 GEMM: g_hpre = g_hcur @ g_w2r ----------------
// Inputs MUST already be tf32-RN-rounded. A has N_PAD rows (scratch) so full-tile
// unguarded cp.async is safe. BM=128, BN=256, BK=16, 512 threads, 16 warps (4x4).
#define CA_LDA 24
#define CA_LDB 264
#define CA_ABUF (128 * CA_LDA)           // floats per A stage
#define CA_BBUF (16 * CA_LDB)            // floats per B stage
#define CA_SMEM ((2 * CA_ABUF + 2 * CA_BBUF) * 4)  // 58368 bytes

__global__ __launch_bounds__(512)
void gemm_tf32_ca()
{
    constexpr int N = 256, K = 256, BK = 16;
    constexpr int S = K / BK;            // 16 stages

    extern __shared__ float sm[];
    float* As = sm;                      // [2][128][CA_LDA]
    float* Bs = sm + 2 * CA_ABUF;        // [2][16][CA_LDB]

    const int tid  = threadIdx.x;
    const int warp = tid >> 5;
    const int wr   = warp >> 2;
    const int wc   = warp & 3;
    const int row0 = blockIdx.y * 128;

    // A: 128 rows x 16 floats = 512 x 16B chunks, 1/thread
    const int ar  = tid >> 2;
    const int ac  = (tid & 3) << 2;      // float offset in row
    // B: 16 rows x 256 floats = 1024 x 16B chunks, 2/thread
    const int br0 = tid >> 6, bc0 = (tid & 63) << 2;
    const int br1 = (tid + 512) >> 6, bc1 = bc0;

    auto issue = [&](int k0, int buf) {
        __pipeline_memcpy_async(&As[(size_t)(buf * 128 + ar) * CA_LDA + ac],
                                &g_hcur[(size_t)(row0 + ar) * K + k0 + ac], 16);
        __pipeline_memcpy_async(&Bs[(size_t)(buf * 16 + br0) * CA_LDB + bc0],
                                &g_w2r[(size_t)(k0 + br0) * N + bc0], 16);
        __pipeline_memcpy_async(&Bs[(size_t)(buf * 16 + br1) * CA_LDB + bc1],
                                &g_w2r[(size_t)(k0 + br1) * N + bc1], 16);
        __pipeline_commit();
    };

    wmma::fragment<wmma::accumulator, 16, 16, 8, float> acc[2][4];
    #pragma unroll
    for (int i = 0; i < 2; i++)
        #pragma unroll
        for (int j = 0; j < 4; j++) wmma::fill_fragment(acc[i][j], 0.0f);

    issue(0, 0);

    for (int s = 0; s < S; s++) {
        int buf = s & 1;
        if (s + 1 < S) {
            issue((s + 1) * BK, 1 - buf);
            __pipeline_wait_prior(1);
        } else {
            __pipeline_wait_prior(0);
        }
        __syncthreads();

        #pragma unroll
        for (int kk = 0; kk < BK; kk += 8) {
            wmma::fragment<wmma::matrix_a, 16, 16, 8, wmma::precision::tf32, wmma::row_major> af[2];
            #pragma unroll
            for (int i = 0; i < 2; i++)
                wmma::load_matrix_sync(af[i], &As[(size_t)(buf * 128 + wr * 32 + i * 16) * CA_LDA + kk], CA_LDA);
            wmma::fragment<wmma::matrix_b, 16, 16, 8, wmma::precision::tf32, wmma::row_major> bf[4];
            #pragma unroll
            for (int j = 0; j < 4; j++)
                wmma::load_matrix_sync(bf[j], &Bs[(size_t)(buf * 16 + kk) * CA_LDB + wc * 64 + j * 16], CA_LDB);
            #pragma unroll
            for (int i = 0; i < 2; i++)
                #pragma unroll
                for (int j = 0; j < 4; j++)
                    wmma::mma_sync(acc[i][j], af[i], bf[j], acc[i][j]);
        }
        __syncthreads();
    }

    #pragma unroll
    for (int i = 0; i < 2; i++)
        #pragma unroll
        for (int j = 0; j < 4; j++) {
            int r = row0 + wr * 32 + i * 16;
            int c = wc * 64 + j * 16;
            wmma::store_matrix_sync(&g_hpre[(size_t)r * N + c], acc[i][j], N, wmma::mem_row_major);
        }
}

// ---------------- tf32 WMMA GEMM, 512 threads (layer 3, BN=128) ----------------
template<int ASEL, int CSEL, int RS>
__global__ __launch_bounds__(512)
void gemm_tf32_512(const float* __restrict__ Aext, const float* __restrict__ B,
                   int M, int N, int K)
{
    constexpr int BM = 128, BN = 128, BK = 32;
    constexpr int LDA = BK + 8;
    constexpr int LDB = BN + 8;

    const float* A = select_in<ASEL>(Aext);
    float* C = select_out<CSEL>(nullptr);

    __shared__ float As[BM][LDA];
    __shared__ float Bs[BK][LDB];

    const int tid  = threadIdx.x;
    const int warp = tid >> 5;
    const int wr   = warp >> 2;
    const int wc   = warp & 3;
    const int row0 = blockIdx.y * BM;
    const int col0 = blockIdx.x * BN;

    wmma::fragment<wmma::accumulator, 16, 16, 8, float> acc[2][2];
    #pragma unroll
    for (int i = 0; i < 2; i++)
        #pragma unroll
        for (int j = 0; j < 2; j++) wmma::fill_fragment(acc[i][j], 0.0f);

    float4 aP[2], bP[2];
    #pragma unroll
    for (int l = 0; l < 2; l++) {
        int lin = tid + l * 512;
        int r = lin >> 3, c4 = (lin & 7) << 2;
        int gr = row0 + r;
        float4 v = make_float4(0.f, 0.f, 0.f, 0.f);
        if (gr < M) {
            v = *(const float4*)&A[(size_t)gr * K + c4];
            if constexpr (RS) {
                float sc = g_deg_out_inv[gr];
                v.x *= sc; v.y *= sc; v.z *= sc; v.w *= sc;
            }
        }
        aP[l] = v;
    }
    #pragma unroll
    for (int l = 0; l < 2; l++) {
        int lin = tid + l * 512;
        int r = lin >> 5, c4 = (lin & 31) << 2;
        bP[l] = *(const float4*)&B[(size_t)r * N + col0 + c4];
    }

    for (int k0 = 0; k0 < K; k0 += BK) {
        #pragma unroll
        for (int l = 0; l < 2; l++) {
            int lin = tid + l * 512;
            int r = lin >> 3, c4 = (lin & 7) << 2;
            As[r][c4 + 0] = wmma::__float_to_tf32(aP[l].x);
            As[r][c4 + 1] = wmma::__float_to_tf32(aP[l].y);
            As[r][c4 + 2] = wmma::__float_to_tf32(aP[l].z);
            As[r][c4 + 3] = wmma::__float_to_tf32(aP[l].w);
        }
        #pragma unroll
        for (int l = 0; l < 2; l++) {
            int lin = tid + l * 512;
            int r = lin >> 5, c4 = (lin & 31) << 2;
            Bs[r][c4 + 0] = wmma::__float_to_tf32(bP[l].x);
            Bs[r][c4 + 1] = wmma::__float_to_tf32(bP[l].y);
            Bs[r][c4 + 2] = wmma::__float_to_tf32(bP[l].z);
            Bs[r][c4 + 3] = wmma::__float_to_tf32(bP[l].w);
        }
        __syncthreads();

        if (k0 + BK < K) {
            #pragma unroll
            for (int l = 0; l < 2; l++) {
                int lin = tid + l * 512;
                int r = lin >> 3, c4 = (lin & 7) << 2;
                int gr = row0 + r;
                float4 v = make_float4(0.f, 0.f, 0.f, 0.f);
                if (gr < M) {
                    v = *(const float4*)&A[(size_t)gr * K + (k0 + BK) + c4];
                    if constexpr (RS) {
                        float sc = g_deg_out_inv[gr];
                        v.x *= sc; v.y *= sc; v.z *= sc; v.w *= sc;
                    }
                }
                aP[l] = v;
            }
            #pragma unroll
            for (int l = 0; l < 2; l++) {
                int lin = tid + l * 512;
                int r = lin >> 5, c4 = (lin & 31) << 2;
                bP[l] = *(const float4*)&B[(size_t)(k0 + BK + r) * N + col0 + c4];
            }
        }

        #pragma unroll
        for (int kk = 0; kk < BK; kk += 8) {
            wmma::fragment<wmma::matrix_a, 16, 16, 8, wmma::precision::tf32, wmma::row_major> af[2];
            #pragma unroll
            for (int i = 0; i < 2; i++)
                wmma::load_matrix_sync(af[i], &As[wr * 32 + i * 16][kk], LDA);
            wmma::fragment<wmma::matrix_b, 16, 16, 8, wmma::precision::tf32, wmma::row_major> bf[2];
            #pragma unroll
            for (int j = 0; j < 2; j++)
                wmma::load_matrix_sync(bf[j], &Bs[kk][wc * 32 + j * 16], LDB);
            #pragma unroll
            for (int i = 0; i < 2; i++)
                #pragma unroll
                for (int j = 0; j < 2; j++)
                    wmma::mma_sync(acc[i][j], af[i], bf[j], acc[i][j]);
        }
        __syncthreads();
    }

    #pragma unroll
    for (int i = 0; i < 2; i++)
        #pragma unroll
        for (int j = 0; j < 2; j++) {
            int r = row0 + wr * 32 + i * 16;
            int c = col0 + wc * 32 + j * 16;
            wmma::store_matrix_sync(&C[(size_t)r * N + c], acc[i][j], N, wmma::mem_row_major);
        }
}

// ---------------- tf32 WMMA GEMM (256 threads; MLP1 BN=64) ----------------
template<int BN, int ASEL, int CSEL, int RS>
__global__ __launch_bounds__(256)
void gemm_tf32_kernel(const float* __restrict__ Aext, const float* __restrict__ B,
                      int M, int N, int K)
{
    constexpr int BM = 128, BK = 32;
    constexpr int LDA = BK + 8;
    constexpr int LDB = BN + 8;
    constexpr int WN  = BN / 2;
    constexpr int NF  = WN / 16;
    constexpr int BL  = BN / 32;
    constexpr int BC4 = BN / 4;

    const float* A = select_in<ASEL>(Aext);
    float* C = select_out<CSEL>(nullptr);

    __shared__ float As[BM][LDA];
    __shared__ float Bs[BK][LDB];

    const int tid  = threadIdx.x;
    const int warp = tid >> 5;
    const int wr   = warp >> 1;
    const int wc   = warp & 1;
    const int row0 = blockIdx.y * BM;
    const int col0 = blockIdx.x * BN;

    wmma::fragment<wmma::accumulator, 16, 16, 8, float> acc[2][NF];
    #pragma unroll
    for (int i = 0; i < 2; i++)
        #pragma unroll
        for (int j = 0; j < NF; j++) wmma::fill_fragment(acc[i][j], 0.0f);

    float4 aP[4], bP[BL];
    #pragma unroll
    for (int l = 0; l < 4; l++) {
        int lin = tid + l * 256;
        int r = lin >> 3, c4 = (lin & 7) << 2;
        int gr = row0 + r;
        float4 v = make_float4(0.f, 0.f, 0.f, 0.f);
        if (gr < M) {
            v = *(const float4*)&A[(size_t)gr * K + c4];
            if constexpr (RS) {
                float sc = g_deg_out_inv[gr];
                v.x *= sc; v.y *= sc; v.z *= sc; v.w *= sc;
            }
        }
        aP[l] = v;
    }
    #pragma unroll
    for (int l = 0; l < BL; l++) {
        int lin = tid + l * 256;
        int r = lin / BC4, c4 = (lin % BC4) * 4;
        bP[l] = *(const float4*)&B[(size_t)r * N + col0 + c4];
    }

    for (int k0 = 0; k0 < K; k0 += BK) {
        #pragma unroll
        for (int l = 0; l < 4; l++) {
            int lin = tid + l * 256;
            int r = lin >> 3, c4 = (lin & 7) << 2;
            As[r][c4 + 0] = wmma::__float_to_tf32(aP[l].x);
            As[r][c4 + 1] = wmma::__float_to_tf32(aP[l].y);
            As[r][c4 + 2] = wmma::__float_to_tf32(aP[l].z);
            As[r][c4 + 3] = wmma::__float_to_tf32(aP[l].w);
        }
        #pragma unroll
        for (int l = 0; l < BL; l++) {
            int lin = tid + l * 256;
            int r = lin / BC4, c4 = (lin % BC4) * 4;
            Bs[r][c4 + 0] = wmma::__float_to_tf32(bP[l].x);
            Bs[r][c4 + 1] = wmma::__float_to_tf32(bP[l].y);
            Bs[r][c4 + 2] = wmma::__float_to_tf32(bP[l].z);
            Bs[r][c4 + 3] = wmma::__float_to_tf32(bP[l].w);
        }
        __syncthreads();

        if (k0 + BK < K) {
            #pragma unroll
            for (int l = 0; l < 4; l++) {
                int lin = tid + l * 256;
                int r = lin >> 3, c4 = (lin & 7) << 2;
                int gr = row0 + r;
                float4 v = make_float4(0.f, 0.f, 0.f, 0.f);
                if (gr < M) {
                    v = *(const float4*)&A[(size_t)gr * K + (k0 + BK) + c4];
                    if constexpr (RS) {
                        float sc = g_deg_out_inv[gr];
                        v.x *= sc; v.y *= sc; v.z *= sc; v.w *= sc;
                    }
                }
                aP[l] = v;
            }
            #pragma unroll
            for (int l = 0; l < BL; l++) {
                int lin = tid + l * 256;
                int r = lin / BC4, c4 = (lin % BC4) * 4;
                bP[l] = *(const float4*)&B[(size_t)(k0 + BK + r) * N + col0 + c4];
            }
        }

        #pragma unroll
        for (int kk = 0; kk < BK; kk += 8) {
            wmma::fragment<wmma::matrix_a, 16, 16, 8, wmma::precision::tf32, wmma::row_major> af[2];
            #pragma unroll
            for (int i = 0; i < 2; i++)
                wmma::load_matrix_sync(af[i], &As[wr * 32 + i * 16][kk], LDA);
            wmma::fragment<wmma::matrix_b, 16, 16, 8, wmma::precision::tf32, wmma::row_major> bf[NF];
            #pragma unroll
            for (int j = 0; j < NF; j++)
                wmma::load_matrix_sync(bf[j], &Bs[kk][wc * WN + j * 16], LDB);
            #pragma unroll
            for (int i = 0; i < 2; i++)
                #pragma unroll
                for (int j = 0; j < NF; j++)
                    wmma::mma_sync(acc[i][j], af[i], bf[j], acc[i][j]);
        }
        __syncthreads();
    }

    #pragma unroll
    for (int i = 0; i < 2; i++)
        #pragma unroll
        for (int j = 0; j < NF; j++) {
            int r = row0 + wr * 32 + i * 16;
            int c = col0 + wc * WN + j * 16;
            wmma::store_matrix_sync(&C[(size_t)r * N + c], acc[i][j], N, wmma::mem_row_major);
        }
}

// ---------------- SIMT GEMM (final MLP layer; guarded d_out store) ----------------
#define GTHREADS 256
template<int BN, int ASEL, int CSEL, int USE_BIAS, int DO_RELU, int ABR>
__global__ __launch_bounds__(GTHREADS)
void gemm128_kernel(const float* __restrict__ Aext, const float* __restrict__ B,
                    float* __restrict__ Cext, int M, int N, int K,
                    const float* __restrict__ bias, const float* __restrict__ abias)
{
    constexpr int BM = 128;
    constexpr int BK = 8;
    constexpr int TM = 8;
    constexpr int TN = BN / 16;

    const float* A = select_in<ASEL>(Aext);
    float* C = select_out<CSEL>(Cext);

    __shared__ float As[BK][BM + 4];
    __shared__ float Bs[BK][BN];

    const int tid = threadIdx.x;
    const int tx = tid % 16;
    const int ty = tid / 16;
    const int row0 = blockIdx.y * BM;
    const int col0 = blockIdx.x * BN;

    const int arow = tid / 2;
    const int ac4  = (tid % 2) * 4;
    const int gA   = row0 + arow;

    const int brow = (BN == 128) ? (tid / 32) : (tid / 16);
    const int bc4  = (BN == 128) ? ((tid % 32) * 4) : ((tid % 16) * 4);
    const bool bactive = (BN == 128) ? true : (tid < 128);

    float acc[TM][TN];
    #pragma unroll
    for (int i = 0; i < TM; i++)
        #pragma unroll
        for (int j = 0; j < TN; j++) acc[i][j] = 0.0f;

    float4 av = make_float4(0.f, 0.f, 0.f, 0.f);
    if (gA < M) {
        av = *(const float4*)&A[(size_t)gA * K + ac4];
        if constexpr (ABR) {
            av.x = fmaxf(av.x + abias[ac4 + 0], 0.f);
            av.y = fmaxf(av.y + abias[ac4 + 1], 0.f);
            av.z = fmaxf(av.z + abias[ac4 + 2], 0.f);
            av.w = fmaxf(av.w + abias[ac4 + 3], 0.f);
        }
    }
    float4 bv = make_float4(0.f, 0.f, 0.f, 0.f);
    if (bactive) bv = *(const float4*)&B[(size_t)brow * N + col0 + bc4];

    for (int k0 = 0; k0 < K; k0 += BK) {
        As[ac4 + 0][arow] = av.x;
        As[ac4 + 1][arow] = av.y;
        As[ac4 + 2][arow] = av.z;
        As[ac4 + 3][arow] = av.w;
        if (bactive) *(float4*)&Bs[brow][bc4] = bv;
        __syncthreads();

        if (k0 + BK < K) {
            av = make_float4(0.f, 0.f, 0.f, 0.f);
            if (gA < M) {
                av = *(const float4*)&A[(size_t)gA * K + (k0 + BK) + ac4];
                if constexpr (ABR) {
                    av.x = fmaxf(av.x + abias[k0 + BK + ac4 + 0], 0.f);
                    av.y = fmaxf(av.y + abias[k0 + BK + ac4 + 1], 0.f);
                    av.z = fmaxf(av.z + abias[k0 + BK + ac4 + 2], 0.f);
                    av.w = fmaxf(av.w + abias[k0 + BK + ac4 + 3], 0.f);
                }
            }
            if (bactive) bv = *(const float4*)&B[(size_t)(k0 + BK + brow) * N + col0 + bc4];
        }

        #pragma unroll
        for (int k = 0; k < BK; k++) {
            float a[TM], b[TN];
            #pragma unroll
            for (int q = 0; q < TM / 4; q++)
                *(float4*)&a[q * 4] = *(const float4*)&As[k][ty * TM + q * 4];
            #pragma unroll
            for (int q = 0; q < TN / 4; q++)
                *(float4*)&b[q * 4] = *(const float4*)&Bs[k][tx * TN + q * 4];
            #pragma unroll
            for (int i = 0; i < TM; i++)
                #pragma unroll
                for (int j = 0; j < TN; j++)
                    acc[i][j] += a[i] * b[j];
        }
        __syncthreads();
    }

    #pragma unroll
    for (int i = 0; i < TM; i++) {
        int r = row0 + ty * TM + i;
        if (r >= M) continue;
        #pragma unroll
        for (int j = 0; j < TN; j += 4) {
            int c = col0 + tx * TN + j;
            float4 v = *(float4*)&acc[i][j];
            if constexpr (USE_BIAS) {
                v.x += bias[c + 0]; v.y += bias[c + 1];
                v.z += bias[c + 2]; v.w += bias[c + 3];
            }
            if constexpr (DO_RELU) {
                v.x = fmaxf(v.x, 0.f); v.y = fmaxf(v.y, 0.f);
                v.z = fmaxf(v.z, 0.f); v.w = fmaxf(v.w, 0.f);
            }
            *(float4*)&C[(size_t)r * N + c] = v;
        }
    }
}

// ---------------- aggregation (float4; ROUND: RN-round output to tf32) ----------------
template<int D, int OSEL, int PRESCALE, int ROUND>
__global__ __launch_bounds__(128)
void agg4_kernel(float* __restrict__ outExt, const float* __restrict__ bias)
{
    constexpr int TPN = D / 4;
    constexpr int NPB = 128 / TPN;
    float* out;
    if constexpr (OSEL == 1) out = g_hcur;
    else out = outExt;

    const int lane = threadIdx.x % TPN;
    const int node = blockIdx.x * NPB + threadIdx.x / TPN;
    if (node >= N_NODES) return;

    const int s = g_row_ptr[node];
    const int e = g_row_ptr[node + 1];
    const float4* __restrict__ hp = (const float4*)g_hpre;
    const int* __restrict__ csr = g_csr_src;

    float4 acc0 = make_float4(0.f, 0.f, 0.f, 0.f);
    float4 acc1 = make_float4(0.f, 0.f, 0.f, 0.f);
    int i = s;
    for (; i + 3 < e; i += 4) {
        int s0 = csr[i];
        int s1 = csr[i + 1];
        int s2 = csr[i + 2];
        int s3 = csr[i + 3];
        float4 v0 = hp[(size_t)s0 * TPN + lane];
        float4 v1 = hp[(size_t)s1 * TPN + lane];
        float4 v2 = hp[(size_t)s2 * TPN + lane];
        float4 v3 = hp[(size_t)s3 * TPN + lane];
        acc0.x += v0.x; acc0.y += v0.y; acc0.z += v0.z; acc0.w += v0.w;
        acc1.x += v1.x; acc1.y += v1.y; acc1.z += v1.z; acc1.w += v1.w;
        acc0.x += v2.x; acc0.y += v2.y; acc0.z += v2.z; acc0.w += v2.w;
        acc1.x += v3.x; acc1.y += v3.y; acc1.z += v3.z; acc1.w += v3.w;
    }
    for (; i < e; i++) {
        int s0 = csr[i];
        float4 v0 = hp[(size_t)s0 * TPN + lane];
        acc0.x += v0.x; acc0.y += v0.y; acc0.z += v0.z; acc0.w += v0.w;
    }
    acc0.x += acc1.x; acc0.y += acc1.y; acc0.z += acc1.z; acc0.w += acc1.w;

    const float sc = g_deg_in_inv[node];
    float osc = 1.0f;
    if constexpr (PRESCALE) osc = g_deg_out_inv[node];
    float4 bb = *(const float4*)&bias[lane * 4];
    float4 r;
    r.x = fmaxf(acc0.x * sc + bb.x, 0.f) * osc;
    r.y = fmaxf(acc0.y * sc + bb.y, 0.f) * osc;
    r.z = fmaxf(acc0.z * sc + bb.z, 0.f) * osc;
    r.w = fmaxf(acc0.w * sc + bb.w, 0.f) * osc;
    if constexpr (ROUND) {
        r.x = wmma::__float_to_tf32(r.x);
        r.y = wmma::__float_to_tf32(r.y);
        r.z = wmma::__float_to_tf32(r.z);
        r.w = wmma::__float_to_tf32(r.w);
    }
    *(float4*)&out[(size_t)node * D + lane * 4] = r;
}

// ---------------- launch ----------------
extern "C" void kernel_launch(void* const* d_in, const int* in_sizes, int n_in,
                              void* d_out, int out_size)
{
    const float* x   = (const float*)d_in[0];
    const int*   ei  = (const int*)d_in[1];
    const float* W1  = (const float*)d_in[2];
    const float* b1  = (const float*)d_in[3];
    const float* W2  = (const float*)d_in[4];
    const float* b2  = (const float*)d_in[5];
    const float* W3  = (const float*)d_in[6];
    const float* b3  = (const float*)d_in[7];
    const float* mW1 = (const float*)d_in[8];
    const float* mb1 = (const float*)d_in[9];
    const float* mW2 = (const float*)d_in[10];
    const float* mb2 = (const float*)d_in[11];

    const int N = in_sizes[0] / D_IN;       // 50000
    const int E = in_sizes[1] / 2;          // 800000

    float* out      = (float*)d_out;
    float* h_last   = (float*)d_out + (size_t)N * D_OUT;

    const int T = 256;
    const int nbN = (N + T - 1) / T;
    const int nbE = (E + T - 1) / T;
    const int nbScan = (N + 1023) / 1024;
    const int tfRows = (N + 127) / 128;     // 391

    // one-time: side stream/events + opt-in to 58.4 KB dynamic smem for gemm_tf32_ca
    static cudaStream_t s2 = nullptr;
    static cudaEvent_t evDeg = nullptr, evCsr = nullptr;
    if (s2 == nullptr) {
        cudaStreamCreateWithFlags(&s2, cudaStreamNonBlocking);
        cudaEventCreateWithFlags(&evDeg, cudaEventDisableTiming);
        cudaEventCreateWithFlags(&evCsr, cudaEventDisableTiming);
        cudaFuncSetAttribute(gemm_tf32_ca,
                             cudaFuncAttributeMaxDynamicSharedMemorySize, CA_SMEM);
    }

    // ---- degrees ----
    zero_counts_kernel<<<nbN, T>>>(N);
    degree_kernel<<<nbE, T>>>(ei, E);
    inv_kernel<<<nbN, T>>>(N);
    cudaEventRecord(evDeg, 0);

    // ---- fork: CSR build + W2 rounding on side stream ----
    cudaStreamWaitEvent(s2, evDeg, 0);
    round_w2_kernel<<<(D_HID2 * D_HID2 + T - 1) / T, T, 0, s2>>>(W2);
    scan1_kernel<<<nbScan, 1024, 0, s2>>>(N);
    scan2_kernel<<<1, 32, 0, s2>>>(nbScan);
    scan3_kernel<<<nbScan, 1024, 0, s2>>>(N);
    copy_fill_kernel<<<nbN, T, 0, s2>>>(N);
    fill_csr_kernel<<<nbE, T, 0, s2>>>(ei, E);
    cudaEventRecord(evCsr, s2);

    // ---- main stream: layer-1 GEMM concurrent with side work ----
    {
        dim3 grid(1, tfRows);
        gemm_tf32_w256<0, 1, 1><<<grid, 512>>>(x, W1, N, D_IN);
    }

    // ---- join; agg1 rounds its output (feeds cp.async gemm2) ----
    cudaStreamWaitEvent(0, evCsr, 0);
    agg4_kernel<D_HID2, 1, 1, 1><<<(N + 1) / 2, 128>>>(nullptr, b1);

    // ---- layer 2: cp.async double-buffered pipeline (experiment) ----
    {
        dim3 grid(1, tfRows);
        gemm_tf32_ca<<<grid, 512, CA_SMEM>>>();
        agg4_kernel<D_HID2, 1, 1, 0><<<(N + 1) / 2, 128>>>(nullptr, b2);
    }
    // ---- layer 3: h_last into d_out ----
    {
        dim3 grid(D_HID / 128, tfRows);
        gemm_tf32_512<1, 1, 0><<<grid, 512>>>(nullptr, W3, N, D_HID, D_HID2);
        agg4_kernel<D_HID, 0, 0, 0><<<(N + 3) / 4, 128>>>(h_last, b3);
    }
    // ---- MLP layer 1 (tf32, raw GEMM into scratch) ----
    {
        dim3 grid(1, tfRows);
        gemm_tf32_kernel<64, 0, 2, 0><<<grid, 256>>>(h_last, mW1, N, D_MLP, D_HID);
    }
    // ---- MLP layer 2 (SIMT, A-side relu(a+mb1), guarded d_out store) ----
    {
        dim3 grid(D_OUT / 64, tfRows);
        gemm128_kernel<64, 2, 0, 1, 0, 1><<<grid, GTHREADS>>>(nullptr, mW2, out,
                                                              N, D_OUT, D_MLP, mb2, mb1);
    }
}